// round 1
// baseline (speedup 1.0000x reference)
#include <cuda_runtime.h>
#include <cuda_bf16.h>
#include <math.h>

// ---------------- problem constants ----------------
#define BATCH 32
#define HH 56
#define WW2 56
#define CC 192
#define HID 768
#define WS 7
#define SS 3
#define NH 6
#define HD 32
#define NTOK 49            // WS*WS
#define NWIN 64            // (56/7)^2
#define MROWS (BATCH*HH*WW2)   // 100352
#define ROWS_PER_BATCH (NWIN*NTOK) // 3136

// ---------------- scratch (device globals: allocation-free) ----------------
__device__ float g_xn  [MROWS*CC];
__device__ float g_qkv [(long)MROWS*3*CC];
__device__ float g_attn[MROWS*CC];
__device__ float g_y   [MROWS*CC];
__device__ float g_xn2 [MROWS*CC];
__device__ float g_h   [(long)MROWS*HID];

// window-row -> image-row index (both gather of rolled xn and scatter of output
// use the same map: roll(-3) then roll(+3) compose with the window permutation)
__device__ __forceinline__ int win2img(int r) {
    int b   = r / ROWS_PER_BATCH;
    int rem = r - b * ROWS_PER_BATCH;
    int w   = rem / NTOK;
    int n   = rem - w * NTOK;
    int i = n / WS, j = n - WS * (n / WS);
    int hs = (w >> 3) * WS + i;
    int ws = (w & 7) * WS + j;
    int h  = hs + SS; if (h  >= HH)  h  -= HH;
    int wc = ws + SS; if (wc >= WW2) wc -= WW2;
    return (b * HH + h) * WW2 + wc;
}

// ---------------- LayerNorm: one warp per row of 192 ----------------
__global__ void ln_kernel(const float* __restrict__ x, const float* __restrict__ g,
                          const float* __restrict__ b, float* __restrict__ o) {
    int row  = blockIdx.x * 8 + (threadIdx.x >> 5);
    int lane = threadIdx.x & 31;
    const float* p = x + (long)row * CC;
    float v[6];
    float s = 0.f;
    #pragma unroll
    for (int i = 0; i < 6; i++) { v[i] = p[lane + 32*i]; s += v[i]; }
    #pragma unroll
    for (int off = 16; off; off >>= 1) s += __shfl_xor_sync(~0u, s, off);
    float mu = s * (1.f/192.f);
    float vs = 0.f;
    #pragma unroll
    for (int i = 0; i < 6; i++) { float d = v[i]-mu; vs += d*d; }
    #pragma unroll
    for (int off = 16; off; off >>= 1) vs += __shfl_xor_sync(~0u, vs, off);
    float r = rsqrtf(vs * (1.f/192.f) + 1e-5f);
    float* op = o + (long)row * CC;
    #pragma unroll
    for (int i = 0; i < 6; i++) {
        int c = lane + 32*i;
        op[c] = (v[i]-mu) * r * g[c] + b[c];
    }
}

// ---------------- generic fp32 GEMM, 64x64x16 tile, 256 threads, 4x4/thread --
#define BM 64
#define BN 64
#define BK 16

enum { EPI_NONE = 0, EPI_GELU = 1, EPI_RES = 2, EPI_SCATTER_RES = 3 };

__device__ __forceinline__ float gelu_f(float x) {
    return 0.5f * x * (1.0f + erff(x * 0.70710678118654752f));
}

template<int EPI, bool GATHER_A>
__global__ void gemm_kernel(const float* __restrict__ A,
                            const float* __restrict__ Bm,
                            const float* __restrict__ bias,
                            float* __restrict__ C,
                            const float* __restrict__ resid,
                            int N, int K) {
    __shared__ float As[BK][BM];
    __shared__ float Bs[BK][BN];
    const int tid = threadIdx.x;
    const int m0 = blockIdx.y * BM;
    const int n0 = blockIdx.x * BN;

    // A tile load: thread -> (row, 4-wide k chunk)
    const int arow = tid >> 2;
    const int akq  = (tid & 3) * 4;
    const int am   = m0 + arow;
    const float* aptr = A + (long)(GATHER_A ? win2img(am) : am) * K + akq;

    // B tile load: thread -> (k row, 4-wide n chunk)
    const int brow = tid >> 4;
    const int bnq  = (tid & 15) * 4;
    const float* bptr = Bm + (long)brow * N + n0 + bnq;

    const int tm = (tid >> 4) * 4;
    const int tn = (tid & 15) * 4;

    float acc[4][4] = {};
    for (int k0 = 0; k0 < K; k0 += BK) {
        float4 a4 = *(const float4*)(aptr + k0);
        float4 b4 = *(const float4*)(bptr + (long)k0 * N);
        As[akq+0][arow] = a4.x;
        As[akq+1][arow] = a4.y;
        As[akq+2][arow] = a4.z;
        As[akq+3][arow] = a4.w;
        *(float4*)&Bs[brow][bnq] = b4;
        __syncthreads();
        #pragma unroll
        for (int kk = 0; kk < BK; kk++) {
            float4 av = *(const float4*)&As[kk][tm];
            float4 bv = *(const float4*)&Bs[kk][tn];
            float a_[4] = {av.x, av.y, av.z, av.w};
            float b_[4] = {bv.x, bv.y, bv.z, bv.w};
            #pragma unroll
            for (int i = 0; i < 4; i++)
                #pragma unroll
                for (int j = 0; j < 4; j++)
                    acc[i][j] += a_[i] * b_[j];
        }
        __syncthreads();
    }

    float4 bias4 = *(const float4*)(bias + n0 + tn);
    float bb[4] = {bias4.x, bias4.y, bias4.z, bias4.w};
    #pragma unroll
    for (int i = 0; i < 4; i++) {
        int m = m0 + tm + i;
        long crow = (EPI == EPI_SCATTER_RES) ? (long)win2img(m) : (long)m;
        float vals[4];
        #pragma unroll
        for (int j = 0; j < 4; j++) {
            float v = acc[i][j] + bb[j];
            if (EPI == EPI_GELU) v = gelu_f(v);
            vals[j] = v;
        }
        if (EPI == EPI_RES || EPI == EPI_SCATTER_RES) {
            const float4 r4 = *(const float4*)(resid + crow * N + n0 + tn);
            vals[0] += r4.x; vals[1] += r4.y; vals[2] += r4.z; vals[3] += r4.w;
        }
        float4 o4 = {vals[0], vals[1], vals[2], vals[3]};
        *(float4*)(C + crow * N + n0 + tn) = o4;
    }
}

// ---------------- windowed attention: one block per (window, head) ----------
__global__ void attn_kernel(const float* __restrict__ qkv,
                            const float* __restrict__ rpb,
                            float* __restrict__ out) {
    const int win = blockIdx.x;      // b*64 + w
    const int h   = blockIdx.y;      // head
    const int w   = win & 63;
    const int wh = w >> 3, wwi = w & 7;
    __shared__ float qs[NTOK][HD];
    __shared__ float ks[NTOK][HD];
    __shared__ float vs[NTOK][HD];
    __shared__ float sc[NTOK][NTOK+1];
    const int tid = threadIdx.x;     // 256
    const long base = (long)win * NTOK;
    const float scale = 0.17677669529663687f;   // 32^-0.5

    for (int idx = tid; idx < NTOK*HD; idx += 256) {
        int n = idx >> 5, c = idx & 31;
        const float* p = qkv + (base + n) * (3*CC) + h*HD + c;
        qs[n][c] = p[0] * scale;
        ks[n][c] = p[CC];
        vs[n][c] = p[2*CC];
    }
    __syncthreads();

    for (int idx = tid; idx < NTOK*NTOK; idx += 256) {
        int n = idx / NTOK, m = idx - NTOK * n;
        float d = 0.f;
        #pragma unroll
        for (int c = 0; c < HD; c++) d += qs[n][c] * ks[m][c];
        int in_ = n / WS, jn = n % WS, im = m / WS, jm = m % WS;
        float bias = rpb[((in_-im+6)*13 + (jn-jm+6)) * NH + h];
        int hn = wh*WS+in_, wn = wwi*WS+jn, hm = wh*WS+im, wm = wwi*WS+jm;
        int cn = (hn < 49 ? 0 : (hn < 53 ? 1 : 2)) * 3 + (wn < 49 ? 0 : (wn < 53 ? 1 : 2));
        int cm = (hm < 49 ? 0 : (hm < 53 ? 1 : 2)) * 3 + (wm < 49 ? 0 : (wm < 53 ? 1 : 2));
        if (cn != cm) bias -= 100.0f;
        sc[n][m] = d + bias;
    }
    __syncthreads();

    int warp = tid >> 5, lane = tid & 31;
    for (int n = warp; n < NTOK; n += 8) {
        float v1 = (lane      < NTOK) ? sc[n][lane]    : -1e30f;
        float v2 = (lane + 32 < NTOK) ? sc[n][lane+32] : -1e30f;
        float mx = fmaxf(v1, v2);
        #pragma unroll
        for (int off = 16; off; off >>= 1) mx = fmaxf(mx, __shfl_xor_sync(~0u, mx, off));
        float e1 = (lane      < NTOK) ? __expf(v1 - mx) : 0.f;
        float e2 = (lane + 32 < NTOK) ? __expf(v2 - mx) : 0.f;
        float s = e1 + e2;
        #pragma unroll
        for (int off = 16; off; off >>= 1) s += __shfl_xor_sync(~0u, s, off);
        float inv = 1.f / s;
        if (lane      < NTOK) sc[n][lane]    = e1 * inv;
        if (lane + 32 < NTOK) sc[n][lane+32] = e2 * inv;
    }
    __syncthreads();

    for (int idx = tid; idx < NTOK*HD; idx += 256) {
        int n = idx >> 5, c = idx & 31;
        float acc = 0.f;
        #pragma unroll
        for (int m = 0; m < NTOK; m++) acc += sc[n][m] * vs[m][c];
        out[(base + n) * CC + h*HD + c] = acc;
    }
}

// ---------------- launch ----------------
extern "C" void kernel_launch(void* const* d_in, const int* in_sizes, int n_in,
                              void* d_out, int out_size) {
    const float* x       = (const float*)d_in[0];
    const float* n1g     = (const float*)d_in[1];
    const float* n1b     = (const float*)d_in[2];
    const float* qkv_w   = (const float*)d_in[3];
    const float* qkv_b   = (const float*)d_in[4];
    const float* rpb     = (const float*)d_in[5];
    const float* proj_w  = (const float*)d_in[6];
    const float* proj_b  = (const float*)d_in[7];
    const float* n2g     = (const float*)d_in[8];
    const float* n2b     = (const float*)d_in[9];
    const float* fc1_w   = (const float*)d_in[10];
    const float* fc1_b   = (const float*)d_in[11];
    const float* fc2_w   = (const float*)d_in[12];
    const float* fc2_b   = (const float*)d_in[13];
    float* out = (float*)d_out;

    float *xn, *qkv, *attn, *y, *xn2, *hbuf;
    cudaGetSymbolAddress((void**)&xn,   g_xn);
    cudaGetSymbolAddress((void**)&qkv,  g_qkv);
    cudaGetSymbolAddress((void**)&attn, g_attn);
    cudaGetSymbolAddress((void**)&y,    g_y);
    cudaGetSymbolAddress((void**)&xn2,  g_xn2);
    cudaGetSymbolAddress((void**)&hbuf, g_h);

    const int mblk = MROWS / BM;   // 1568

    // 1) LN1
    ln_kernel<<<MROWS/8, 256>>>(x, n1g, n1b, xn);
    // 2) QKV gemm (gather rolled windows)
    gemm_kernel<EPI_NONE, true><<<dim3(3*CC/BN, mblk), 256>>>(xn, qkv_w, qkv_b, qkv, nullptr, 3*CC, CC);
    // 3) attention
    attn_kernel<<<dim3(BATCH*NWIN, NH), 256>>>(qkv, rpb, attn);
    // 4) proj gemm + scatter + residual
    gemm_kernel<EPI_SCATTER_RES, false><<<dim3(CC/BN, mblk), 256>>>(attn, proj_w, proj_b, y, x, CC, CC);
    // 5) LN2
    ln_kernel<<<MROWS/8, 256>>>(y, n2g, n2b, xn2);
    // 6) FC1 + GELU
    gemm_kernel<EPI_GELU, false><<<dim3(HID/BN, mblk), 256>>>(xn2, fc1_w, fc1_b, hbuf, nullptr, HID, CC);
    // 7) FC2 + residual -> out
    gemm_kernel<EPI_RES, false><<<dim3(CC/BN, mblk), 256>>>(hbuf, fc2_w, fc2_b, out, y, CC, HID);
}

// round 4
// speedup vs baseline: 1.6811x; 1.6811x over previous
// R4 = R2-fixed tf32 tensor-core kernel, re-benched after R3 infra failure.
#include <cuda_runtime.h>
#include <cuda_bf16.h>
#include <math.h>
#include <stdint.h>

// ---------------- problem constants ----------------
#define BATCH 32
#define HH 56
#define WW2 56
#define CC 192
#define HID 768
#define WS 7
#define SS 3
#define NH 6
#define HD 32
#define NTOK 49            // WS*WS
#define NWIN 64            // (56/7)^2
#define MROWS (BATCH*HH*WW2)   // 100352
#define ROWS_PER_BATCH (NWIN*NTOK) // 3136

// ---------------- scratch (device globals: allocation-free) ----------------
__device__ float g_xn  [MROWS*CC];
__device__ float g_qkv [(long)MROWS*3*CC];
__device__ float g_attn[MROWS*CC];
__device__ float g_y   [MROWS*CC];
__device__ float g_xn2 [MROWS*CC];
__device__ float g_h   [(long)MROWS*HID];

// window-row -> image-row index (gather of rolled xn and scatter of output use
// the same map: the two rolls compose with the window permutation identically)
__device__ __forceinline__ int win2img(int r) {
    int b   = r / ROWS_PER_BATCH;
    int rem = r - b * ROWS_PER_BATCH;
    int w   = rem / NTOK;
    int n   = rem - w * NTOK;
    int i = n / WS, j = n - WS * (n / WS);
    int hs = (w >> 3) * WS + i;
    int ws = (w & 7) * WS + j;
    int h  = hs + SS; if (h  >= HH)  h  -= HH;
    int wc = ws + SS; if (wc >= WW2) wc -= WW2;
    return (b * HH + h) * WW2 + wc;
}

// ---------------- LayerNorm: one warp per row of 192 ----------------
__global__ void ln_kernel(const float* __restrict__ x, const float* __restrict__ g,
                          const float* __restrict__ b, float* __restrict__ o) {
    int row  = blockIdx.x * 8 + (threadIdx.x >> 5);
    int lane = threadIdx.x & 31;
    const float* p = x + (long)row * CC;
    float v[6];
    float s = 0.f;
    #pragma unroll
    for (int i = 0; i < 6; i++) { v[i] = p[lane + 32*i]; s += v[i]; }
    #pragma unroll
    for (int off = 16; off; off >>= 1) s += __shfl_xor_sync(~0u, s, off);
    float mu = s * (1.f/192.f);
    float vs = 0.f;
    #pragma unroll
    for (int i = 0; i < 6; i++) { float d = v[i]-mu; vs += d*d; }
    #pragma unroll
    for (int off = 16; off; off >>= 1) vs += __shfl_xor_sync(~0u, vs, off);
    float r = rsqrtf(vs * (1.f/192.f) + 1e-5f);
    float* op = o + (long)row * CC;
    #pragma unroll
    for (int i = 0; i < 6; i++) {
        int c = lane + 32*i;
        op[c] = (v[i]-mu) * r * g[c] + b[c];
    }
}

// ---------------- tf32 tensor-core GEMM ----------------
#define BM 128
#define BN 64
#define BK 16
#define SBS 72                 // Bs row stride (floats): banks 8k+n -> conflict-free
#define ASZ (BM*16)            // 2048 floats per A buffer
#define BSZ (BK*SBS)           // 1152 floats per B buffer

enum { EPI_NONE = 0, EPI_GELU = 1, EPI_RES = 2, EPI_SCATTER_RES = 3 };

__device__ __forceinline__ float gelu_f(float x) {
    return 0.5f * x * (1.0f + erff(x * 0.70710678118654752f));
}
__device__ __forceinline__ uint32_t to_tf32(float x) {
    uint32_t r; asm("cvt.rna.tf32.f32 %0, %1;" : "=r"(r) : "f"(x)); return r;
}
__device__ __forceinline__ void mma_tf32(float* c, const uint32_t* a, const uint32_t* b) {
    asm volatile("mma.sync.aligned.m16n8k8.row.col.f32.tf32.tf32.f32 "
        "{%0,%1,%2,%3},{%4,%5,%6,%7},{%8,%9},{%0,%1,%2,%3};"
        : "+f"(c[0]), "+f"(c[1]), "+f"(c[2]), "+f"(c[3])
        : "r"(a[0]), "r"(a[1]), "r"(a[2]), "r"(a[3]), "r"(b[0]), "r"(b[1]));
}
__device__ __forceinline__ void ldmatrix4(uint32_t* r, const float* p) {
    uint32_t addr = (uint32_t)__cvta_generic_to_shared(p);
    asm volatile("ldmatrix.sync.aligned.m8n8.x4.shared.b16 {%0,%1,%2,%3}, [%4];"
        : "=r"(r[0]), "=r"(r[1]), "=r"(r[2]), "=r"(r[3]) : "r"(addr));
}

template<int EPI, bool GATHER_A>
__global__ void __launch_bounds__(256) tgemm(const float* __restrict__ A,
                                             const float* __restrict__ Bm,
                                             const float* __restrict__ bias,
                                             float* __restrict__ C,
                                             const float* __restrict__ resid,
                                             int N, int K) {
    __shared__ float As[2*ASZ];
    __shared__ float Bs[2*BSZ];
    const int tid = threadIdx.x, lane = tid & 31, warp = tid >> 5;
    const int m0 = blockIdx.y * BM;
    const int n0 = blockIdx.x * BN;

    // ---- gmem A tile load: thread -> row tid/2, cols (tid&1)*8 .. +7 (2 float4)
    const int arow = tid >> 1;
    const int acol = (tid & 1) * 8;
    const float* ag = A + (long)(GATHER_A ? win2img(m0 + arow) : (m0 + arow)) * K + acol;
    const int a_sw = (arow >> 1) & 3;
    const int aoff0 = arow * 16 + 4 * (((acol >> 2) + 0) ^ a_sw);
    const int aoff1 = arow * 16 + 4 * (((acol >> 2) + 1) ^ a_sw);

    // ---- gmem B tile load: thread -> k row tid/16, n cols (tid&15)*4 (1 float4)
    const int bkrow = tid >> 4;
    const int bncol = (tid & 15) * 4;
    const float* bg = Bm + (long)bkrow * N + n0 + bncol;
    const int boff = bkrow * SBS + bncol;

    // ---- warp tiling: 4 (m) x 2 (n) warps, each 32x32
    const int m_warp = (warp & 3) * 32;
    const int n_warp = (warp >> 2) * 32;
    const int mloc0 = m_warp + (lane & 15);
    const int mloc1 = mloc0 + 16;
    const int sw0 = (mloc0 >> 1) & 3;
    const int sw1 = (mloc1 >> 1) & 3;
    const int khalf = lane >> 4;          // ldmatrix quadrant k-half select
    const int bk_lo = lane & 3;           // B frag k within step
    const int bn    = n_warp + (lane >> 2);

    float acc[2][4][4];
    #pragma unroll
    for (int i = 0; i < 2; i++)
        #pragma unroll
        for (int j = 0; j < 4; j++)
            #pragma unroll
            for (int l = 0; l < 4; l++) acc[i][j][l] = 0.f;

    float4 pa0 = *(const float4*)ag;
    float4 pa1 = *(const float4*)(ag + 4);
    float4 pb  = *(const float4*)bg;

    const int nk = K / BK;
    int bufA = 0, bufB = 0;
    for (int it = 0; it < nk; ++it) {
        uint4 ca0, ca1, cb;
        ca0.x = to_tf32(pa0.x); ca0.y = to_tf32(pa0.y); ca0.z = to_tf32(pa0.z); ca0.w = to_tf32(pa0.w);
        ca1.x = to_tf32(pa1.x); ca1.y = to_tf32(pa1.y); ca1.z = to_tf32(pa1.z); ca1.w = to_tf32(pa1.w);
        cb.x  = to_tf32(pb.x);  cb.y  = to_tf32(pb.y);  cb.z  = to_tf32(pb.z);  cb.w  = to_tf32(pb.w);
        *(uint4*)&As[bufA + aoff0] = ca0;
        *(uint4*)&As[bufA + aoff1] = ca1;
        *(uint4*)&Bs[bufB + boff]  = cb;
        __syncthreads();

        if (it + 1 < nk) {
            ag += BK; bg += (long)BK * N;
            pa0 = *(const float4*)ag;
            pa1 = *(const float4*)(ag + 4);
            pb  = *(const float4*)bg;
        }

        #pragma unroll
        for (int ks = 0; ks < 2; ks++) {
            uint32_t afr[2][4];
            ldmatrix4(afr[0], &As[bufA + mloc0 * 16 + 4 * ((ks*2 + khalf) ^ sw0)]);
            ldmatrix4(afr[1], &As[bufA + mloc1 * 16 + 4 * ((ks*2 + khalf) ^ sw1)]);
            uint32_t bfr[4][2];
            const float* bp = &Bs[bufB + (ks*8 + bk_lo) * SBS + bn];
            #pragma unroll
            for (int nt = 0; nt < 4; nt++) {
                bfr[nt][0] = __float_as_uint(bp[nt*8]);
                bfr[nt][1] = __float_as_uint(bp[4*SBS + nt*8]);
            }
            #pragma unroll
            for (int mt = 0; mt < 2; mt++)
                #pragma unroll
                for (int nt = 0; nt < 4; nt++)
                    mma_tf32(acc[mt][nt], afr[mt], bfr[nt]);
        }
        bufA ^= ASZ; bufB ^= BSZ;
        __syncthreads();
    }

    // ---- epilogue
    const int g  = lane >> 2;
    const int tg = lane & 3;
    #pragma unroll
    for (int mt = 0; mt < 2; mt++) {
        #pragma unroll
        for (int rh = 0; rh < 2; rh++) {
            int m = m0 + m_warp + mt*16 + rh*8 + g;
            long crow = (EPI == EPI_SCATTER_RES) ? (long)win2img(m) : (long)m;
            #pragma unroll
            for (int nt = 0; nt < 4; nt++) {
                int col = n0 + n_warp + nt*8 + tg*2;
                float2 bb = *(const float2*)(bias + col);
                float v0 = acc[mt][nt][rh*2 + 0] + bb.x;
                float v1 = acc[mt][nt][rh*2 + 1] + bb.y;
                if (EPI == EPI_GELU) { v0 = gelu_f(v0); v1 = gelu_f(v1); }
                if (EPI == EPI_RES || EPI == EPI_SCATTER_RES) {
                    float2 r2 = *(const float2*)(resid + crow * N + col);
                    v0 += r2.x; v1 += r2.y;
                }
                float2 o2 = {v0, v1};
                *(float2*)(C + crow * N + col) = o2;
            }
        }
    }
}

// ---------------- windowed attention: one block per (window, head) ----------
__global__ void attn_kernel(const float* __restrict__ qkv,
                            const float* __restrict__ rpb,
                            float* __restrict__ out) {
    const int win = blockIdx.x;      // b*64 + w
    const int h   = blockIdx.y;      // head
    const int w   = win & 63;
    const int wh = w >> 3, wwi = w & 7;
    __shared__ float qs[NTOK][HD];
    __shared__ float ks[NTOK][HD];
    __shared__ float vs[NTOK][HD];
    __shared__ float sc[NTOK][NTOK+1];
    const int tid = threadIdx.x;     // 256
    const long base = (long)win * NTOK;
    const float scale = 0.17677669529663687f;   // 32^-0.5

    for (int idx = tid; idx < NTOK*HD; idx += 256) {
        int n = idx >> 5, c = idx & 31;
        const float* p = qkv + (base + n) * (3*CC) + h*HD + c;
        qs[n][c] = p[0] * scale;
        ks[n][c] = p[CC];
        vs[n][c] = p[2*CC];
    }
    __syncthreads();

    for (int idx = tid; idx < NTOK*NTOK; idx += 256) {
        int n = idx / NTOK, m = idx - NTOK * n;
        float d = 0.f;
        #pragma unroll
        for (int c = 0; c < HD; c++) d += qs[n][c] * ks[m][c];
        int in_ = n / WS, jn = n % WS, im = m / WS, jm = m % WS;
        float bias = rpb[((in_-im+6)*13 + (jn-jm+6)) * NH + h];
        int hn = wh*WS+in_, wn = wwi*WS+jn, hm = wh*WS+im, wm = wwi*WS+jm;
        int cn = (hn < 49 ? 0 : (hn < 53 ? 1 : 2)) * 3 + (wn < 49 ? 0 : (wn < 53 ? 1 : 2));
        int cm = (hm < 49 ? 0 : (hm < 53 ? 1 : 2)) * 3 + (wm < 49 ? 0 : (wm < 53 ? 1 : 2));
        if (cn != cm) bias -= 100.0f;
        sc[n][m] = d + bias;
    }
    __syncthreads();

    int warp = tid >> 5, lane = tid & 31;
    for (int n = warp; n < NTOK; n += 8) {
        float v1 = (lane      < NTOK) ? sc[n][lane]    : -1e30f;
        float v2 = (lane + 32 < NTOK) ? sc[n][lane+32] : -1e30f;
        float mx = fmaxf(v1, v2);
        #pragma unroll
        for (int off = 16; off; off >>= 1) mx = fmaxf(mx, __shfl_xor_sync(~0u, mx, off));
        float e1 = (lane      < NTOK) ? __expf(v1 - mx) : 0.f;
        float e2 = (lane + 32 < NTOK) ? __expf(v2 - mx) : 0.f;
        float s = e1 + e2;
        #pragma unroll
        for (int off = 16; off; off >>= 1) s += __shfl_xor_sync(~0u, s, off);
        float inv = 1.f / s;
        if (lane      < NTOK) sc[n][lane]    = e1 * inv;
        if (lane + 32 < NTOK) sc[n][lane+32] = e2 * inv;
    }
    __syncthreads();

    for (int idx = tid; idx < NTOK*HD; idx += 256) {
        int n = idx >> 5, c = idx & 31;
        float acc = 0.f;
        #pragma unroll
        for (int m = 0; m < NTOK; m++) acc += sc[n][m] * vs[m][c];
        out[(base + n) * CC + h*HD + c] = acc;
    }
}

// ---------------- launch ----------------
extern "C" void kernel_launch(void* const* d_in, const int* in_sizes, int n_in,
                              void* d_out, int out_size) {
    const float* x       = (const float*)d_in[0];
    const float* n1g     = (const float*)d_in[1];
    const float* n1b     = (const float*)d_in[2];
    const float* qkv_w   = (const float*)d_in[3];
    const float* qkv_b   = (const float*)d_in[4];
    const float* rpb     = (const float*)d_in[5];
    const float* proj_w  = (const float*)d_in[6];
    const float* proj_b  = (const float*)d_in[7];
    const float* n2g     = (const float*)d_in[8];
    const float* n2b     = (const float*)d_in[9];
    const float* fc1_w   = (const float*)d_in[10];
    const float* fc1_b   = (const float*)d_in[11];
    const float* fc2_w   = (const float*)d_in[12];
    const float* fc2_b   = (const float*)d_in[13];
    float* out = (float*)d_out;

    float *xn, *qkv, *attn, *y, *xn2, *hbuf;
    cudaGetSymbolAddress((void**)&xn,   g_xn);
    cudaGetSymbolAddress((void**)&qkv,  g_qkv);
    cudaGetSymbolAddress((void**)&attn, g_attn);
    cudaGetSymbolAddress((void**)&y,    g_y);
    cudaGetSymbolAddress((void**)&xn2,  g_xn2);
    cudaGetSymbolAddress((void**)&hbuf, g_h);

    const int mblk = MROWS / BM;   // 784

    // 1) LN1
    ln_kernel<<<MROWS/8, 256>>>(x, n1g, n1b, xn);
    // 2) QKV gemm (gather rolled windows)
    tgemm<EPI_NONE, true><<<dim3(3*CC/BN, mblk), 256>>>(xn, qkv_w, qkv_b, qkv, nullptr, 3*CC, CC);
    // 3) attention
    attn_kernel<<<dim3(BATCH*NWIN, NH), 256>>>(qkv, rpb, attn);
    // 4) proj gemm + scatter + residual
    tgemm<EPI_SCATTER_RES, false><<<dim3(CC/BN, mblk), 256>>>(attn, proj_w, proj_b, y, x, CC, CC);
    // 5) LN2
    ln_kernel<<<MROWS/8, 256>>>(y, n2g, n2b, xn2);
    // 6) FC1 + GELU
    tgemm<EPI_GELU, false><<<dim3(HID/BN, mblk), 256>>>(xn2, fc1_w, fc1_b, hbuf, nullptr, HID, CC);
    // 7) FC2 + residual -> out
    tgemm<EPI_RES, false><<<dim3(CC/BN, mblk), 256>>>(hbuf, fc2_w, fc2_b, out, y, CC, HID);
}

// round 5
// speedup vs baseline: 2.1865x; 1.3006x over previous
// R5: bf16 mma.m16n8k16 GEMMs, all-ldmatrix fragments, cp.async tiles,
// bf16 intermediate tensors (residual chain kept fp32).
#include <cuda_runtime.h>
#include <cuda_bf16.h>
#include <math.h>
#include <stdint.h>

#define BATCH 32
#define HH 56
#define WW2 56
#define CC 192
#define HID 768
#define WS 7
#define SS 3
#define NH 6
#define HD 32
#define NTOK 49
#define NWIN 64
#define MROWS (BATCH*HH*WW2)        // 100352
#define ROWS_PER_BATCH (NWIN*NTOK)  // 3136

typedef __nv_bfloat16 bf16;
typedef __nv_bfloat162 bf162;

// ---------------- scratch ----------------
__device__ bf16  g_xn_h [MROWS*CC];
__device__ bf16  g_qkv_h[(long)MROWS*3*CC];
__device__ bf16  g_attn_h[MROWS*CC];
__device__ float g_y    [MROWS*CC];
__device__ bf16  g_xn2_h[MROWS*CC];
__device__ bf16  g_h_h  [(long)MROWS*HID];
__device__ bf16  g_wq[CC*3*CC];
__device__ bf16  g_wp[CC*CC];
__device__ bf16  g_w1[CC*HID];
__device__ bf16  g_w2[HID*CC];

__device__ __forceinline__ int win2img(int r) {
    int b   = r / ROWS_PER_BATCH;
    int rem = r - b * ROWS_PER_BATCH;
    int w   = rem / NTOK;
    int n   = rem - w * NTOK;
    int i = n / WS, j = n - WS * (n / WS);
    int hs = (w >> 3) * WS + i;
    int ws = (w & 7) * WS + j;
    int h  = hs + SS; if (h  >= HH)  h  -= HH;
    int wc = ws + SS; if (wc >= WW2) wc -= WW2;
    return (b * HH + h) * WW2 + wc;
}

// ---------------- fp32 -> bf16 weight conversion ----------------
__global__ void f2bf_kernel(const float* __restrict__ s, bf16* __restrict__ d, int n) {
    int i = blockIdx.x * 256 + threadIdx.x;
    if (i < n) d[i] = __float2bfloat16(s[i]);
}

// ---------------- LayerNorm: warp per row, bf16 out ----------------
__global__ void ln_kernel(const float* __restrict__ x, const float* __restrict__ g,
                          const float* __restrict__ b, bf16* __restrict__ o) {
    int row  = blockIdx.x * 8 + (threadIdx.x >> 5);
    int lane = threadIdx.x & 31;
    const float* p = x + (long)row * CC;
    float v[6];
    float s = 0.f;
    #pragma unroll
    for (int i = 0; i < 6; i++) { v[i] = p[lane + 32*i]; s += v[i]; }
    #pragma unroll
    for (int off = 16; off; off >>= 1) s += __shfl_xor_sync(~0u, s, off);
    float mu = s * (1.f/192.f);
    float vs = 0.f;
    #pragma unroll
    for (int i = 0; i < 6; i++) { float d = v[i]-mu; vs += d*d; }
    #pragma unroll
    for (int off = 16; off; off >>= 1) vs += __shfl_xor_sync(~0u, vs, off);
    float r = rsqrtf(vs * (1.f/192.f) + 1e-5f);
    bf16* op = o + (long)row * CC;
    #pragma unroll
    for (int i = 0; i < 6; i++) {
        int c = lane + 32*i;
        op[c] = __float2bfloat16((v[i]-mu) * r * g[c] + b[c]);
    }
}

// ---------------- bf16 tensor-core GEMM ----------------
#define BM 128
#define BN 64
#define BK 32
#define A_BYTES (BM*64)      // 8192 per buffer (row = 32 bf16 = 64B)
#define B_BYTES (BK*128)     // 4096 per buffer (row = 64 bf16 = 128B)

enum { EPI_NONE = 0, EPI_GELU = 1, EPI_RES = 2, EPI_SCATTER_RES = 3 };

__device__ __forceinline__ float gelu_f(float x) {
    return 0.5f * x * (1.0f + erff(x * 0.70710678118654752f));
}
__device__ __forceinline__ void mma_bf16(float* c, const uint32_t* a, const uint32_t* b) {
    asm volatile("mma.sync.aligned.m16n8k16.row.col.f32.bf16.bf16.f32 "
        "{%0,%1,%2,%3},{%4,%5,%6,%7},{%8,%9},{%0,%1,%2,%3};"
        : "+f"(c[0]), "+f"(c[1]), "+f"(c[2]), "+f"(c[3])
        : "r"(a[0]), "r"(a[1]), "r"(a[2]), "r"(a[3]), "r"(b[0]), "r"(b[1]));
}
__device__ __forceinline__ void ldmx4(uint32_t* r, uint32_t addr) {
    asm volatile("ldmatrix.sync.aligned.m8n8.x4.shared.b16 {%0,%1,%2,%3}, [%4];"
        : "=r"(r[0]), "=r"(r[1]), "=r"(r[2]), "=r"(r[3]) : "r"(addr));
}
__device__ __forceinline__ void ldmx4t(uint32_t* r, uint32_t addr) {
    asm volatile("ldmatrix.sync.aligned.m8n8.x4.trans.shared.b16 {%0,%1,%2,%3}, [%4];"
        : "=r"(r[0]), "=r"(r[1]), "=r"(r[2]), "=r"(r[3]) : "r"(addr));
}
__device__ __forceinline__ void cp16(uint32_t smem, const void* g) {
    asm volatile("cp.async.cg.shared.global [%0], [%1], 16;" :: "r"(smem), "l"(g));
}

template<int EPI, bool GATHER_A, bool OUT_BF16>
__global__ void __launch_bounds__(256) tgemm(const bf16* __restrict__ A,
                                             const bf16* __restrict__ Bm,
                                             const float* __restrict__ bias,
                                             void* __restrict__ Cv,
                                             const float* __restrict__ resid,
                                             int N, int K) {
    __shared__ char smemA[2*A_BYTES];
    __shared__ char smemB[2*B_BYTES];
    const uint32_t sA = (uint32_t)__cvta_generic_to_shared(smemA);
    const uint32_t sB = (uint32_t)__cvta_generic_to_shared(smemB);
    const int tid = threadIdx.x, lane = tid & 31, warp = tid >> 5;
    const int m0 = blockIdx.y * BM;
    const int n0 = blockIdx.x * BN;

    // A tile: thread -> row tid/2, 16-elem half (tid&1); 2 cp16 per iter
    const int arow = tid >> 1;
    const int ac0  = (tid & 1) * 2;                 // first chunk idx (of 4)
    const int aswr = (arow >> 1) & 3;
    const bf16* agp = A + (long)(GATHER_A ? win2img(m0 + arow) : (m0 + arow)) * K + (tid & 1) * 16;
    const uint32_t adst0 = arow*64 + (uint32_t)(((ac0+0) ^ aswr)*16);
    const uint32_t adst1 = arow*64 + (uint32_t)(((ac0+1) ^ aswr)*16);

    // B tile: thread -> k row tid/8, n chunk tid&7; 1 cp16 per iter
    const int bk = tid >> 3;
    const int bc = tid & 7;
    const bf16* bgp = Bm + (long)bk * N + n0 + bc * 8;
    const uint32_t bdst = bk*128 + (uint32_t)((bc ^ (bk & 7))*16);

    // warps: 4(m) x 2(n), warp tile 32x32
    const int m_warp = (warp & 3) * 32;
    const int n_warp = (warp >> 2) * 32;

    float acc[2][4][4];
    #pragma unroll
    for (int i = 0; i < 2; i++)
        #pragma unroll
        for (int j = 0; j < 4; j++)
            #pragma unroll
            for (int l = 0; l < 4; l++) acc[i][j][l] = 0.f;

    const int nk = K / BK;

    // prologue: stage 0
    {
        cp16(sA + adst0, agp);
        cp16(sA + adst1, agp + 8);
        cp16(sB + bdst,  bgp);
        asm volatile("cp.async.commit_group;" ::: "memory");
    }

    for (int it = 0; it < nk; ++it) {
        if (it + 1 < nk) {
            const int nb = (it + 1) & 1;
            const bf16* ag = agp + (it + 1) * BK;
            const bf16* bg = bgp + (long)(it + 1) * BK * N;
            cp16(sA + nb*A_BYTES + adst0, ag);
            cp16(sA + nb*A_BYTES + adst1, ag + 8);
            cp16(sB + nb*B_BYTES + bdst,  bg);
            asm volatile("cp.async.commit_group;" ::: "memory");
            asm volatile("cp.async.wait_group 1;" ::: "memory");
        } else {
            asm volatile("cp.async.wait_group 0;" ::: "memory");
        }
        __syncthreads();

        const uint32_t aB = sA + (it & 1)*A_BYTES;
        const uint32_t bB = sB + (it & 1)*B_BYTES;
        #pragma unroll
        for (int ksub = 0; ksub < 2; ksub++) {
            uint32_t afr[2][4];
            #pragma unroll
            for (int mt = 0; mt < 2; mt++) {
                int row = m_warp + mt*16 + (lane & 15);
                int ch  = ksub*2 + (lane >> 4);
                ldmx4(afr[mt], aB + row*64 + ((ch ^ ((row>>1)&3))*16));
            }
            uint32_t bfr[4][2];
            #pragma unroll
            for (int np = 0; np < 2; np++) {
                int k  = ksub*16 + ((lane>>3)&1)*8 + (lane&7);
                int cn = (n_warp>>3) + np*2 + (lane>>4);
                uint32_t r[4];
                ldmx4t(r, bB + k*128 + ((cn ^ (k&7))*16));
                bfr[np*2+0][0] = r[0]; bfr[np*2+0][1] = r[1];
                bfr[np*2+1][0] = r[2]; bfr[np*2+1][1] = r[3];
            }
            #pragma unroll
            for (int mt = 0; mt < 2; mt++)
                #pragma unroll
                for (int nt = 0; nt < 4; nt++)
                    mma_bf16(acc[mt][nt], afr[mt], bfr[nt]);
        }
        __syncthreads();
    }

    // ---- epilogue
    const int g  = lane >> 2;
    const int tg = lane & 3;
    float* Cf = (float*)Cv;
    bf16*  Cb = (bf16*)Cv;
    #pragma unroll
    for (int mt = 0; mt < 2; mt++) {
        #pragma unroll
        for (int rh = 0; rh < 2; rh++) {
            int m = m0 + m_warp + mt*16 + rh*8 + g;
            long crow = (EPI == EPI_SCATTER_RES) ? (long)win2img(m) : (long)m;
            #pragma unroll
            for (int nt = 0; nt < 4; nt++) {
                int col = n0 + n_warp + nt*8 + tg*2;
                float2 bb = *(const float2*)(bias + col);
                float v0 = acc[mt][nt][rh*2 + 0] + bb.x;
                float v1 = acc[mt][nt][rh*2 + 1] + bb.y;
                if (EPI == EPI_GELU) { v0 = gelu_f(v0); v1 = gelu_f(v1); }
                if (EPI == EPI_RES || EPI == EPI_SCATTER_RES) {
                    float2 r2 = *(const float2*)(resid + crow * N + col);
                    v0 += r2.x; v1 += r2.y;
                }
                if (OUT_BF16) {
                    bf162 o; o.x = __float2bfloat16(v0); o.y = __float2bfloat16(v1);
                    *(bf162*)(Cb + crow * N + col) = o;
                } else {
                    float2 o2 = {v0, v1};
                    *(float2*)(Cf + crow * N + col) = o2;
                }
            }
        }
    }
}

// ---------------- windowed attention (bf16 in/out, fp32 math) --------------
__global__ void attn_kernel(const bf16* __restrict__ qkv,
                            const float* __restrict__ rpb,
                            bf16* __restrict__ out) {
    const int win = blockIdx.x;
    const int h   = blockIdx.y;
    const int w   = win & 63;
    const int wh = w >> 3, wwi = w & 7;
    __shared__ float qs[NTOK][HD];
    __shared__ float ks[NTOK][HD];
    __shared__ float vs[NTOK][HD];
    __shared__ float sc[NTOK][NTOK+1];
    const int tid = threadIdx.x;
    const long base = (long)win * NTOK;
    const float scale = 0.17677669529663687f;

    for (int idx = tid; idx < NTOK*HD/2; idx += 256) {
        int n = idx >> 4, c = (idx & 15) * 2;
        const bf16* p = qkv + (base + n) * (3*CC) + h*HD + c;
        bf162 q2 = *(const bf162*)(p);
        bf162 k2 = *(const bf162*)(p + CC);
        bf162 v2 = *(const bf162*)(p + 2*CC);
        qs[n][c]   = __bfloat162float(q2.x) * scale;
        qs[n][c+1] = __bfloat162float(q2.y) * scale;
        ks[n][c]   = __bfloat162float(k2.x);
        ks[n][c+1] = __bfloat162float(k2.y);
        vs[n][c]   = __bfloat162float(v2.x);
        vs[n][c+1] = __bfloat162float(v2.y);
    }
    __syncthreads();

    for (int idx = tid; idx < NTOK*NTOK; idx += 256) {
        int n = idx / NTOK, m = idx - NTOK * n;
        float d = 0.f;
        #pragma unroll
        for (int c = 0; c < HD; c++) d += qs[n][c] * ks[m][c];
        int in_ = n / WS, jn = n % WS, im = m / WS, jm = m % WS;
        float bias = rpb[((in_-im+6)*13 + (jn-jm+6)) * NH + h];
        int hn = wh*WS+in_, wn = wwi*WS+jn, hm = wh*WS+im, wm = wwi*WS+jm;
        int cn = (hn < 49 ? 0 : (hn < 53 ? 1 : 2)) * 3 + (wn < 49 ? 0 : (wn < 53 ? 1 : 2));
        int cm = (hm < 49 ? 0 : (hm < 53 ? 1 : 2)) * 3 + (wm < 49 ? 0 : (wm < 53 ? 1 : 2));
        if (cn != cm) bias -= 100.0f;
        sc[n][m] = d + bias;
    }
    __syncthreads();

    int warp = tid >> 5, lane = tid & 31;
    for (int n = warp; n < NTOK; n += 8) {
        float v1 = (lane      < NTOK) ? sc[n][lane]    : -1e30f;
        float v2 = (lane + 32 < NTOK) ? sc[n][lane+32] : -1e30f;
        float mx = fmaxf(v1, v2);
        #pragma unroll
        for (int off = 16; off; off >>= 1) mx = fmaxf(mx, __shfl_xor_sync(~0u, mx, off));
        float e1 = (lane      < NTOK) ? __expf(v1 - mx) : 0.f;
        float e2 = (lane + 32 < NTOK) ? __expf(v2 - mx) : 0.f;
        float s = e1 + e2;
        #pragma unroll
        for (int off = 16; off; off >>= 1) s += __shfl_xor_sync(~0u, s, off);
        float inv = 1.f / s;
        if (lane      < NTOK) sc[n][lane]    = e1 * inv;
        if (lane + 32 < NTOK) sc[n][lane+32] = e2 * inv;
    }
    __syncthreads();

    for (int idx = tid; idx < NTOK*HD/2; idx += 256) {
        int n = idx >> 4, c = (idx & 15) * 2;
        float a0 = 0.f, a1 = 0.f;
        #pragma unroll
        for (int m = 0; m < NTOK; m++) {
            float p = sc[n][m];
            a0 += p * vs[m][c];
            a1 += p * vs[m][c+1];
        }
        bf162 o; o.x = __float2bfloat16(a0); o.y = __float2bfloat16(a1);
        *(bf162*)(out + (base + n) * CC + h*HD + c) = o;
    }
}

// ---------------- launch ----------------
extern "C" void kernel_launch(void* const* d_in, const int* in_sizes, int n_in,
                              void* d_out, int out_size) {
    const float* x       = (const float*)d_in[0];
    const float* n1g     = (const float*)d_in[1];
    const float* n1b     = (const float*)d_in[2];
    const float* qkv_w   = (const float*)d_in[3];
    const float* qkv_b   = (const float*)d_in[4];
    const float* rpb     = (const float*)d_in[5];
    const float* proj_w  = (const float*)d_in[6];
    const float* proj_b  = (const float*)d_in[7];
    const float* n2g     = (const float*)d_in[8];
    const float* n2b     = (const float*)d_in[9];
    const float* fc1_w   = (const float*)d_in[10];
    const float* fc1_b   = (const float*)d_in[11];
    const float* fc2_w   = (const float*)d_in[12];
    const float* fc2_b   = (const float*)d_in[13];
    float* out = (float*)d_out;

    bf16 *xn, *qkv, *attn, *xn2, *hbuf, *wq, *wp, *w1, *w2;
    float *y;
    cudaGetSymbolAddress((void**)&xn,   g_xn_h);
    cudaGetSymbolAddress((void**)&qkv,  g_qkv_h);
    cudaGetSymbolAddress((void**)&attn, g_attn_h);
    cudaGetSymbolAddress((void**)&y,    g_y);
    cudaGetSymbolAddress((void**)&xn2,  g_xn2_h);
    cudaGetSymbolAddress((void**)&hbuf, g_h_h);
    cudaGetSymbolAddress((void**)&wq,   g_wq);
    cudaGetSymbolAddress((void**)&wp,   g_wp);
    cudaGetSymbolAddress((void**)&w1,   g_w1);
    cudaGetSymbolAddress((void**)&w2,   g_w2);

    // weight conversions (cheap, once per replay)
    f2bf_kernel<<<(CC*3*CC+255)/256, 256>>>(qkv_w, wq, CC*3*CC);
    f2bf_kernel<<<(CC*CC+255)/256,   256>>>(proj_w, wp, CC*CC);
    f2bf_kernel<<<(CC*HID+255)/256,  256>>>(fc1_w, w1, CC*HID);
    f2bf_kernel<<<(HID*CC+255)/256,  256>>>(fc2_w, w2, HID*CC);

    const int mblk = MROWS / BM;   // 784

    ln_kernel<<<MROWS/8, 256>>>(x, n1g, n1b, xn);
    tgemm<EPI_NONE, true, true><<<dim3(3*CC/BN, mblk), 256>>>(xn, wq, qkv_b, qkv, nullptr, 3*CC, CC);
    attn_kernel<<<dim3(BATCH*NWIN, NH), 256>>>(qkv, rpb, attn);
    tgemm<EPI_SCATTER_RES, false, false><<<dim3(CC/BN, mblk), 256>>>(attn, wp, proj_b, y, x, CC, CC);
    ln_kernel<<<MROWS/8, 256>>>(y, n2g, n2b, xn2);
    tgemm<EPI_GELU, false, true><<<dim3(HID/BN, mblk), 256>>>(xn2, w1, fc1_b, hbuf, nullptr, HID, CC);
    tgemm<EPI_RES, false, false><<<dim3(CC/BN, mblk), 256>>>(hbuf, w2, fc2_b, out, y, CC, HID);
}

// round 7
// speedup vs baseline: 3.4936x; 1.5978x over previous
// R7 = R6 resubmission after infra failure (attention bank-conflict fix,
// single-sync GEMM mainloop, merged weight-convert). No functional changes.
#include <cuda_runtime.h>
#include <cuda_bf16.h>
#include <math.h>
#include <stdint.h>

#define BATCH 32
#define HH 56
#define WW2 56
#define CC 192
#define HID 768
#define WS 7
#define SS 3
#define NH 6
#define HD 32
#define NTOK 49
#define NWIN 64
#define MROWS (BATCH*HH*WW2)        // 100352
#define ROWS_PER_BATCH (NWIN*NTOK)  // 3136

typedef __nv_bfloat16 bf16;
typedef __nv_bfloat162 bf162;

// ---------------- scratch ----------------
__device__ bf16  g_xn_h [MROWS*CC];
__device__ bf16  g_qkv_h[(long)MROWS*3*CC];
__device__ bf16  g_attn_h[MROWS*CC];
__device__ float g_y    [MROWS*CC];
__device__ bf16  g_xn2_h[MROWS*CC];
__device__ bf16  g_h_h  [(long)MROWS*HID];
__device__ bf16  g_wq[CC*3*CC];
__device__ bf16  g_wp[CC*CC];
__device__ bf16  g_w1[CC*HID];
__device__ bf16  g_w2[HID*CC];

__device__ __forceinline__ int win2img(int r) {
    int b   = r / ROWS_PER_BATCH;
    int rem = r - b * ROWS_PER_BATCH;
    int w   = rem / NTOK;
    int n   = rem - w * NTOK;
    int i = n / WS, j = n - WS * (n / WS);
    int hs = (w >> 3) * WS + i;
    int ws = (w & 7) * WS + j;
    int h  = hs + SS; if (h  >= HH)  h  -= HH;
    int wc = ws + SS; if (wc >= WW2) wc -= WW2;
    return (b * HH + h) * WW2 + wc;
}

// ---------------- fp32 -> bf16 conversion for all four weights ------------
#define WQ_N (CC*3*CC)
#define WP_N (CC*CC)
#define W1_N (CC*HID)
#define W2_N (HID*CC)
#define WTOT (WQ_N+WP_N+W1_N+W2_N)
__global__ void f2bf_all(const float* __restrict__ s0, const float* __restrict__ s1,
                         const float* __restrict__ s2, const float* __restrict__ s3,
                         bf16* d0, bf16* d1, bf16* d2, bf16* d3) {
    int i = blockIdx.x * 256 + threadIdx.x;
    if (i < WQ_N) { d0[i] = __float2bfloat16(s0[i]); return; }
    i -= WQ_N;
    if (i < WP_N) { d1[i] = __float2bfloat16(s1[i]); return; }
    i -= WP_N;
    if (i < W1_N) { d2[i] = __float2bfloat16(s2[i]); return; }
    i -= W1_N;
    if (i < W2_N) { d3[i] = __float2bfloat16(s3[i]); }
}

// ---------------- LayerNorm: warp per row, bf16 out ----------------
__global__ void ln_kernel(const float* __restrict__ x, const float* __restrict__ g,
                          const float* __restrict__ b, bf16* __restrict__ o) {
    int row  = blockIdx.x * 8 + (threadIdx.x >> 5);
    int lane = threadIdx.x & 31;
    const float* p = x + (long)row * CC;
    float v[6];
    float s = 0.f;
    #pragma unroll
    for (int i = 0; i < 6; i++) { v[i] = p[lane + 32*i]; s += v[i]; }
    #pragma unroll
    for (int off = 16; off; off >>= 1) s += __shfl_xor_sync(~0u, s, off);
    float mu = s * (1.f/192.f);
    float vs = 0.f;
    #pragma unroll
    for (int i = 0; i < 6; i++) { float d = v[i]-mu; vs += d*d; }
    #pragma unroll
    for (int off = 16; off; off >>= 1) vs += __shfl_xor_sync(~0u, vs, off);
    float r = rsqrtf(vs * (1.f/192.f) + 1e-5f);
    bf16* op = o + (long)row * CC;
    #pragma unroll
    for (int i = 0; i < 6; i++) {
        int c = lane + 32*i;
        op[c] = __float2bfloat16((v[i]-mu) * r * g[c] + b[c]);
    }
}

// ---------------- bf16 tensor-core GEMM ----------------
#define BM 128
#define BN 64
#define BK 32
#define A_BYTES (BM*64)      // 8192 per buffer (row = 32 bf16 = 64B)
#define B_BYTES (BK*128)     // 4096 per buffer (row = 64 bf16 = 128B)

enum { EPI_NONE = 0, EPI_GELU = 1, EPI_RES = 2, EPI_SCATTER_RES = 3 };

__device__ __forceinline__ float gelu_f(float x) {
    return 0.5f * x * (1.0f + erff(x * 0.70710678118654752f));
}
__device__ __forceinline__ void mma_bf16(float* c, const uint32_t* a, const uint32_t* b) {
    asm volatile("mma.sync.aligned.m16n8k16.row.col.f32.bf16.bf16.f32 "
        "{%0,%1,%2,%3},{%4,%5,%6,%7},{%8,%9},{%0,%1,%2,%3};"
        : "+f"(c[0]), "+f"(c[1]), "+f"(c[2]), "+f"(c[3])
        : "r"(a[0]), "r"(a[1]), "r"(a[2]), "r"(a[3]), "r"(b[0]), "r"(b[1]));
}
__device__ __forceinline__ void ldmx4(uint32_t* r, uint32_t addr) {
    asm volatile("ldmatrix.sync.aligned.m8n8.x4.shared.b16 {%0,%1,%2,%3}, [%4];"
        : "=r"(r[0]), "=r"(r[1]), "=r"(r[2]), "=r"(r[3]) : "r"(addr));
}
__device__ __forceinline__ void ldmx4t(uint32_t* r, uint32_t addr) {
    asm volatile("ldmatrix.sync.aligned.m8n8.x4.trans.shared.b16 {%0,%1,%2,%3}, [%4];"
        : "=r"(r[0]), "=r"(r[1]), "=r"(r[2]), "=r"(r[3]) : "r"(addr));
}
__device__ __forceinline__ void cp16(uint32_t smem, const void* g) {
    asm volatile("cp.async.cg.shared.global [%0], [%1], 16;" :: "r"(smem), "l"(g));
}

template<int EPI, bool GATHER_A, bool OUT_BF16>
__global__ void __launch_bounds__(256) tgemm(const bf16* __restrict__ A,
                                             const bf16* __restrict__ Bm,
                                             const float* __restrict__ bias,
                                             void* __restrict__ Cv,
                                             const float* __restrict__ resid,
                                             int N, int K) {
    __shared__ char smemA[2*A_BYTES];
    __shared__ char smemB[2*B_BYTES];
    const uint32_t sA = (uint32_t)__cvta_generic_to_shared(smemA);
    const uint32_t sB = (uint32_t)__cvta_generic_to_shared(smemB);
    const int tid = threadIdx.x, lane = tid & 31, warp = tid >> 5;
    const int m0 = blockIdx.y * BM;
    const int n0 = blockIdx.x * BN;

    // A tile: thread -> row tid/2, 16-elem half (tid&1); 2 cp16 per iter
    const int arow = tid >> 1;
    const int ac0  = (tid & 1) * 2;
    const int aswr = (arow >> 1) & 3;
    const bf16* agp = A + (long)(GATHER_A ? win2img(m0 + arow) : (m0 + arow)) * K + (tid & 1) * 16;
    const uint32_t adst0 = arow*64 + (uint32_t)(((ac0+0) ^ aswr)*16);
    const uint32_t adst1 = arow*64 + (uint32_t)(((ac0+1) ^ aswr)*16);

    // B tile: thread -> k row tid/8, n chunk tid&7; 1 cp16 per iter
    const int bk = tid >> 3;
    const int bc = tid & 7;
    const bf16* bgp = Bm + (long)bk * N + n0 + bc * 8;
    const uint32_t bdst = bk*128 + (uint32_t)((bc ^ (bk & 7))*16);

    // warps: 4(m) x 2(n), warp tile 32x32
    const int m_warp = (warp & 3) * 32;
    const int n_warp = (warp >> 2) * 32;

    float acc[2][4][4];
    #pragma unroll
    for (int i = 0; i < 2; i++)
        #pragma unroll
        for (int j = 0; j < 4; j++)
            #pragma unroll
            for (int l = 0; l < 4; l++) acc[i][j][l] = 0.f;

    const int nk = K / BK;

    // prologue: stage 0
    cp16(sA + adst0, agp);
    cp16(sA + adst1, agp + 8);
    cp16(sB + bdst,  bgp);
    asm volatile("cp.async.commit_group;" ::: "memory");

    for (int it = 0; it < nk; ++it) {
        asm volatile("cp.async.wait_group 0;" ::: "memory");
        __syncthreads();
        // prefetch next stage AFTER the barrier: its target buffer was consumed
        // in iteration it-1, and the barrier proves every warp finished it.
        if (it + 1 < nk) {
            const int nb = (it + 1) & 1;
            const bf16* ag = agp + (it + 1) * BK;
            const bf16* bg = bgp + (long)(it + 1) * BK * N;
            cp16(sA + nb*A_BYTES + adst0, ag);
            cp16(sA + nb*A_BYTES + adst1, ag + 8);
            cp16(sB + nb*B_BYTES + bdst,  bg);
            asm volatile("cp.async.commit_group;" ::: "memory");
        }

        const uint32_t aB = sA + (it & 1)*A_BYTES;
        const uint32_t bB = sB + (it & 1)*B_BYTES;
        #pragma unroll
        for (int ksub = 0; ksub < 2; ksub++) {
            uint32_t afr[2][4];
            #pragma unroll
            for (int mt = 0; mt < 2; mt++) {
                int row = m_warp + mt*16 + (lane & 15);
                int ch  = ksub*2 + (lane >> 4);
                ldmx4(afr[mt], aB + row*64 + ((ch ^ ((row>>1)&3))*16));
            }
            uint32_t bfr[4][2];
            #pragma unroll
            for (int np = 0; np < 2; np++) {
                int k  = ksub*16 + ((lane>>3)&1)*8 + (lane&7);
                int cn = (n_warp>>3) + np*2 + (lane>>4);
                uint32_t r[4];
                ldmx4t(r, bB + k*128 + ((cn ^ (k&7))*16));
                bfr[np*2+0][0] = r[0]; bfr[np*2+0][1] = r[1];
                bfr[np*2+1][0] = r[2]; bfr[np*2+1][1] = r[3];
            }
            #pragma unroll
            for (int mt = 0; mt < 2; mt++)
                #pragma unroll
                for (int nt = 0; nt < 4; nt++)
                    mma_bf16(acc[mt][nt], afr[mt], bfr[nt]);
        }
    }

    // ---- epilogue
    const int g  = lane >> 2;
    const int tg = lane & 3;
    float* Cf = (float*)Cv;
    bf16*  Cb = (bf16*)Cv;
    #pragma unroll
    for (int mt = 0; mt < 2; mt++) {
        #pragma unroll
        for (int rh = 0; rh < 2; rh++) {
            int m = m0 + m_warp + mt*16 + rh*8 + g;
            long crow = (EPI == EPI_SCATTER_RES) ? (long)win2img(m) : (long)m;
            #pragma unroll
            for (int nt = 0; nt < 4; nt++) {
                int col = n0 + n_warp + nt*8 + tg*2;
                float2 bb = *(const float2*)(bias + col);
                float v0 = acc[mt][nt][rh*2 + 0] + bb.x;
                float v1 = acc[mt][nt][rh*2 + 1] + bb.y;
                if (EPI == EPI_GELU) { v0 = gelu_f(v0); v1 = gelu_f(v1); }
                if (EPI == EPI_RES || EPI == EPI_SCATTER_RES) {
                    float2 r2 = *(const float2*)(resid + crow * N + col);
                    v0 += r2.x; v1 += r2.y;
                }
                if (OUT_BF16) {
                    bf162 o; o.x = __float2bfloat16(v0); o.y = __float2bfloat16(v1);
                    *(bf162*)(Cb + crow * N + col) = o;
                } else {
                    float2 o2 = {v0, v1};
                    *(float2*)(Cf + crow * N + col) = o2;
                }
            }
        }
    }
}

// ---------------- windowed attention (bank-conflict-free smem) -------------
#define QKP 33    // odd row stride for qs/ks: bank = (m + c) % 32, conflict-free

__global__ void attn_kernel(const bf16* __restrict__ qkv,
                            const float* __restrict__ rpb,
                            bf16* __restrict__ out) {
    const int win = blockIdx.x;
    const int h   = blockIdx.y;
    const int w   = win & 63;
    const int wh = w >> 3, wwi = w & 7;
    __shared__ float qs[NTOK][QKP];
    __shared__ float ks[NTOK][QKP];
    __shared__ float vs[NTOK][HD];
    __shared__ float sc[NTOK][NTOK+1];
    const int tid = threadIdx.x;
    const long base = (long)win * NTOK;
    const float scale = 0.17677669529663687f;

    for (int idx = tid; idx < NTOK*HD; idx += 256) {
        int n = idx >> 5, c = idx & 31;
        const bf16* p = qkv + (base + n) * (3*CC) + h*HD + c;
        qs[n][c] = __bfloat162float(p[0]) * scale;
        ks[n][c] = __bfloat162float(p[CC]);
        vs[n][c] = __bfloat162float(p[2*CC]);
    }
    __syncthreads();

    for (int idx = tid; idx < NTOK*NTOK; idx += 256) {
        int n = idx / NTOK, m = idx - NTOK * n;
        float d = 0.f;
        #pragma unroll
        for (int c = 0; c < HD; c++) d += qs[n][c] * ks[m][c];
        int in_ = n / WS, jn = n % WS, im = m / WS, jm = m % WS;
        float bias = rpb[((in_-im+6)*13 + (jn-jm+6)) * NH + h];
        int hn = wh*WS+in_, wn = wwi*WS+jn, hm = wh*WS+im, wm = wwi*WS+jm;
        int cn = (hn < 49 ? 0 : (hn < 53 ? 1 : 2)) * 3 + (wn < 49 ? 0 : (wn < 53 ? 1 : 2));
        int cm = (hm < 49 ? 0 : (hm < 53 ? 1 : 2)) * 3 + (wm < 49 ? 0 : (wm < 53 ? 1 : 2));
        if (cn != cm) bias -= 100.0f;
        sc[n][m] = d + bias;
    }
    __syncthreads();

    int warp = tid >> 5, lane = tid & 31;
    for (int n = warp; n < NTOK; n += 8) {
        float v1 = (lane      < NTOK) ? sc[n][lane]    : -1e30f;
        float v2 = (lane + 32 < NTOK) ? sc[n][lane+32] : -1e30f;
        float mx = fmaxf(v1, v2);
        #pragma unroll
        for (int off = 16; off; off >>= 1) mx = fmaxf(mx, __shfl_xor_sync(~0u, mx, off));
        float e1 = (lane      < NTOK) ? __expf(v1 - mx) : 0.f;
        float e2 = (lane + 32 < NTOK) ? __expf(v2 - mx) : 0.f;
        float s = e1 + e2;
        #pragma unroll
        for (int off = 16; off; off >>= 1) s += __shfl_xor_sync(~0u, s, off);
        float inv = 1.f / s;
        if (lane      < NTOK) sc[n][lane]    = e1 * inv;
        if (lane + 32 < NTOK) sc[n][lane+32] = e2 * inv;
    }
    __syncthreads();

    for (int idx = tid; idx < NTOK*HD/2; idx += 256) {
        int n = idx >> 4, c = (idx & 15) * 2;
        float a0 = 0.f, a1 = 0.f;
        #pragma unroll
        for (int m = 0; m < NTOK; m++) {
            float p = sc[n][m];
            float2 v2 = *(const float2*)&vs[m][c];
            a0 += p * v2.x;
            a1 += p * v2.y;
        }
        bf162 o; o.x = __float2bfloat16(a0); o.y = __float2bfloat16(a1);
        *(bf162*)(out + (base + n) * CC + h*HD + c) = o;
    }
}

// ---------------- launch ----------------
extern "C" void kernel_launch(void* const* d_in, const int* in_sizes, int n_in,
                              void* d_out, int out_size) {
    const float* x       = (const float*)d_in[0];
    const float* n1g     = (const float*)d_in[1];
    const float* n1b     = (const float*)d_in[2];
    const float* qkv_w   = (const float*)d_in[3];
    const float* qkv_b   = (const float*)d_in[4];
    const float* rpb     = (const float*)d_in[5];
    const float* proj_w  = (const float*)d_in[6];
    const float* proj_b  = (const float*)d_in[7];
    const float* n2g     = (const float*)d_in[8];
    const float* n2b     = (const float*)d_in[9];
    const float* fc1_w   = (const float*)d_in[10];
    const float* fc1_b   = (const float*)d_in[11];
    const float* fc2_w   = (const float*)d_in[12];
    const float* fc2_b   = (const float*)d_in[13];
    float* out = (float*)d_out;

    bf16 *xn, *qkv, *attn, *xn2, *hbuf, *wq, *wp, *w1, *w2;
    float *y;
    cudaGetSymbolAddress((void**)&xn,   g_xn_h);
    cudaGetSymbolAddress((void**)&qkv,  g_qkv_h);
    cudaGetSymbolAddress((void**)&attn, g_attn_h);
    cudaGetSymbolAddress((void**)&y,    g_y);
    cudaGetSymbolAddress((void**)&xn2,  g_xn2_h);
    cudaGetSymbolAddress((void**)&hbuf, g_h_h);
    cudaGetSymbolAddress((void**)&wq,   g_wq);
    cudaGetSymbolAddress((void**)&wp,   g_wp);
    cudaGetSymbolAddress((void**)&w1,   g_w1);
    cudaGetSymbolAddress((void**)&w2,   g_w2);

    f2bf_all<<<(WTOT+255)/256, 256>>>(qkv_w, proj_w, fc1_w, fc2_w, wq, wp, w1, w2);

    const int mblk = MROWS / BM;   // 784

    ln_kernel<<<MROWS/8, 256>>>(x, n1g, n1b, xn);
    tgemm<EPI_NONE, true, true><<<dim3(3*CC/BN, mblk), 256>>>(xn, wq, qkv_b, qkv, nullptr, 3*CC, CC);
    attn_kernel<<<dim3(BATCH*NWIN, NH), 256>>>(qkv, rpb, attn);
    tgemm<EPI_SCATTER_RES, false, false><<<dim3(CC/BN, mblk), 256>>>(attn, wp, proj_b, y, x, CC, CC);
    ln_kernel<<<MROWS/8, 256>>>(y, n2g, n2b, xn2);
    tgemm<EPI_GELU, false, true><<<dim3(HID/BN, mblk), 256>>>(xn2, w1, fc1_b, hbuf, nullptr, HID, CC);
    tgemm<EPI_RES, false, false><<<dim3(CC/BN, mblk), 256>>>(hbuf, w2, fc2_b, out, y, CC, HID);
}

// round 8
// speedup vs baseline: 5.8449x; 1.6730x over previous
// R8: tensor-core (bf16 mma) windowed attention; precomputed bias table;
// GEMM/LN pipeline unchanged from R7 (verified).
#include <cuda_runtime.h>
#include <cuda_bf16.h>
#include <math.h>
#include <stdint.h>

#define BATCH 32
#define HH 56
#define WW2 56
#define CC 192
#define HID 768
#define WS 7
#define SS 3
#define NH 6
#define HD 32
#define NTOK 49
#define NWIN 64
#define MROWS (BATCH*HH*WW2)        // 100352
#define ROWS_PER_BATCH (NWIN*NTOK)  // 3136

typedef __nv_bfloat16 bf16;
typedef __nv_bfloat162 bf162;

// ---------------- scratch ----------------
__device__ bf16  g_xn_h [MROWS*CC];
__device__ bf16  g_qkv_h[(long)MROWS*3*CC];
__device__ bf16  g_attn_h[MROWS*CC];
__device__ float g_y    [MROWS*CC];
__device__ bf16  g_xn2_h[MROWS*CC];
__device__ bf16  g_h_h  [(long)MROWS*HID];
__device__ bf16  g_wq[CC*3*CC];
__device__ bf16  g_wp[CC*CC];
__device__ bf16  g_w1[CC*HID];
__device__ bf16  g_w2[HID*CC];
__device__ float g_bias[4*NH*64*64];    // [class][head][64][64]

__device__ __forceinline__ int win2img(int r) {
    int b   = r / ROWS_PER_BATCH;
    int rem = r - b * ROWS_PER_BATCH;
    int w   = rem / NTOK;
    int n   = rem - w * NTOK;
    int i = n / WS, j = n - WS * (n / WS);
    int hs = (w >> 3) * WS + i;
    int ws = (w & 7) * WS + j;
    int h  = hs + SS; if (h  >= HH)  h  -= HH;
    int wc = ws + SS; if (wc >= WW2) wc -= WW2;
    return (b * HH + h) * WW2 + wc;
}

// ---------------- fp32 -> bf16 conversion for all four weights ------------
#define WQ_N (CC*3*CC)
#define WP_N (CC*CC)
#define W1_N (CC*HID)
#define W2_N (HID*CC)
#define WTOT (WQ_N+WP_N+W1_N+W2_N)
__global__ void f2bf_all(const float* __restrict__ s0, const float* __restrict__ s1,
                         const float* __restrict__ s2, const float* __restrict__ s3,
                         bf16* d0, bf16* d1, bf16* d2, bf16* d3) {
    int i = blockIdx.x * 256 + threadIdx.x;
    if (i < WQ_N) { d0[i] = __float2bfloat16(s0[i]); return; }
    i -= WQ_N;
    if (i < WP_N) { d1[i] = __float2bfloat16(s1[i]); return; }
    i -= WP_N;
    if (i < W1_N) { d2[i] = __float2bfloat16(s2[i]); return; }
    i -= W1_N;
    if (i < W2_N) { d3[i] = __float2bfloat16(s3[i]); }
}

// ---------------- attention bias table: [class][head][64][64] -------------
__global__ void bias_precompute(const float* __restrict__ rpb) {
    int idx = blockIdx.x * 256 + threadIdx.x;   // 4*6*4096 total
    int cls = idx / (NH*4096);
    int rem = idx - cls*NH*4096;
    int h   = rem >> 12;
    int p   = rem & 4095;
    int n = p >> 6, m = p & 63;
    float v;
    if (m >= NTOK) v = -1e9f;          // masked pad cols: excluded from softmax
    else if (n >= NTOK) v = 0.f;       // pad rows: never stored, keep finite
    else {
        int in_ = n / WS, jn = n % WS, im = m / WS, jm = m % WS;
        v = rpb[((in_-im+6)*13 + (jn-jm+6))*NH + h];
        int rE = cls >> 1, cE = cls & 1;
        int rn = rE ? (in_ < 4 ? 1 : 2) : 0;
        int cn = cE ? (jn  < 4 ? 1 : 2) : 0;
        int rm = rE ? (im  < 4 ? 1 : 2) : 0;
        int cm = cE ? (jm  < 4 ? 1 : 2) : 0;
        if (rn*3+cn != rm*3+cm) v -= 100.f;
    }
    g_bias[idx] = v;
}

// ---------------- LayerNorm: warp per row, bf16 out ----------------
__global__ void ln_kernel(const float* __restrict__ x, const float* __restrict__ g,
                          const float* __restrict__ b, bf16* __restrict__ o) {
    int row  = blockIdx.x * 8 + (threadIdx.x >> 5);
    int lane = threadIdx.x & 31;
    const float* p = x + (long)row * CC;
    float v[6];
    float s = 0.f;
    #pragma unroll
    for (int i = 0; i < 6; i++) { v[i] = p[lane + 32*i]; s += v[i]; }
    #pragma unroll
    for (int off = 16; off; off >>= 1) s += __shfl_xor_sync(~0u, s, off);
    float mu = s * (1.f/192.f);
    float vs = 0.f;
    #pragma unroll
    for (int i = 0; i < 6; i++) { float d = v[i]-mu; vs += d*d; }
    #pragma unroll
    for (int off = 16; off; off >>= 1) vs += __shfl_xor_sync(~0u, vs, off);
    float r = rsqrtf(vs * (1.f/192.f) + 1e-5f);
    bf16* op = o + (long)row * CC;
    #pragma unroll
    for (int i = 0; i < 6; i++) {
        int c = lane + 32*i;
        op[c] = __float2bfloat16((v[i]-mu) * r * g[c] + b[c]);
    }
}

// ---------------- bf16 mma helpers ----------------
__device__ __forceinline__ void mma_bf16(float* c, const uint32_t* a, const uint32_t* b) {
    asm volatile("mma.sync.aligned.m16n8k16.row.col.f32.bf16.bf16.f32 "
        "{%0,%1,%2,%3},{%4,%5,%6,%7},{%8,%9},{%0,%1,%2,%3};"
        : "+f"(c[0]), "+f"(c[1]), "+f"(c[2]), "+f"(c[3])
        : "r"(a[0]), "r"(a[1]), "r"(a[2]), "r"(a[3]), "r"(b[0]), "r"(b[1]));
}
__device__ __forceinline__ void ldmx4(uint32_t* r, uint32_t addr) {
    asm volatile("ldmatrix.sync.aligned.m8n8.x4.shared.b16 {%0,%1,%2,%3}, [%4];"
        : "=r"(r[0]), "=r"(r[1]), "=r"(r[2]), "=r"(r[3]) : "r"(addr));
}
__device__ __forceinline__ void ldmx4t(uint32_t* r, uint32_t addr) {
    asm volatile("ldmatrix.sync.aligned.m8n8.x4.trans.shared.b16 {%0,%1,%2,%3}, [%4];"
        : "=r"(r[0]), "=r"(r[1]), "=r"(r[2]), "=r"(r[3]) : "r"(addr));
}
__device__ __forceinline__ void cp16(uint32_t smem, const void* g) {
    asm volatile("cp.async.cg.shared.global [%0], [%1], 16;" :: "r"(smem), "l"(g));
}
__device__ __forceinline__ uint32_t packbf(float lo, float hi) {
    bf162 t; t.x = __float2bfloat16(lo); t.y = __float2bfloat16(hi);
    return *(uint32_t*)&t;
}

// ---------------- bf16 tensor-core GEMM (unchanged, verified) -------------
#define BM 128
#define BN 64
#define BK 32
#define A_BYTES (BM*64)
#define B_BYTES (BK*128)

enum { EPI_NONE = 0, EPI_GELU = 1, EPI_RES = 2, EPI_SCATTER_RES = 3 };

__device__ __forceinline__ float gelu_f(float x) {
    return 0.5f * x * (1.0f + erff(x * 0.70710678118654752f));
}

template<int EPI, bool GATHER_A, bool OUT_BF16>
__global__ void __launch_bounds__(256) tgemm(const bf16* __restrict__ A,
                                             const bf16* __restrict__ Bm,
                                             const float* __restrict__ bias,
                                             void* __restrict__ Cv,
                                             const float* __restrict__ resid,
                                             int N, int K) {
    __shared__ char smemA[2*A_BYTES];
    __shared__ char smemB[2*B_BYTES];
    const uint32_t sA = (uint32_t)__cvta_generic_to_shared(smemA);
    const uint32_t sB = (uint32_t)__cvta_generic_to_shared(smemB);
    const int tid = threadIdx.x, lane = tid & 31, warp = tid >> 5;
    const int m0 = blockIdx.y * BM;
    const int n0 = blockIdx.x * BN;

    const int arow = tid >> 1;
    const int ac0  = (tid & 1) * 2;
    const int aswr = (arow >> 1) & 3;
    const bf16* agp = A + (long)(GATHER_A ? win2img(m0 + arow) : (m0 + arow)) * K + (tid & 1) * 16;
    const uint32_t adst0 = arow*64 + (uint32_t)(((ac0+0) ^ aswr)*16);
    const uint32_t adst1 = arow*64 + (uint32_t)(((ac0+1) ^ aswr)*16);

    const int bk = tid >> 3;
    const int bc = tid & 7;
    const bf16* bgp = Bm + (long)bk * N + n0 + bc * 8;
    const uint32_t bdst = bk*128 + (uint32_t)((bc ^ (bk & 7))*16);

    const int m_warp = (warp & 3) * 32;
    const int n_warp = (warp >> 2) * 32;

    float acc[2][4][4];
    #pragma unroll
    for (int i = 0; i < 2; i++)
        #pragma unroll
        for (int j = 0; j < 4; j++)
            #pragma unroll
            for (int l = 0; l < 4; l++) acc[i][j][l] = 0.f;

    const int nk = K / BK;

    cp16(sA + adst0, agp);
    cp16(sA + adst1, agp + 8);
    cp16(sB + bdst,  bgp);
    asm volatile("cp.async.commit_group;" ::: "memory");

    for (int it = 0; it < nk; ++it) {
        asm volatile("cp.async.wait_group 0;" ::: "memory");
        __syncthreads();
        if (it + 1 < nk) {
            const int nb = (it + 1) & 1;
            const bf16* ag = agp + (it + 1) * BK;
            const bf16* bg = bgp + (long)(it + 1) * BK * N;
            cp16(sA + nb*A_BYTES + adst0, ag);
            cp16(sA + nb*A_BYTES + adst1, ag + 8);
            cp16(sB + nb*B_BYTES + bdst,  bg);
            asm volatile("cp.async.commit_group;" ::: "memory");
        }

        const uint32_t aB = sA + (it & 1)*A_BYTES;
        const uint32_t bB = sB + (it & 1)*B_BYTES;
        #pragma unroll
        for (int ksub = 0; ksub < 2; ksub++) {
            uint32_t afr[2][4];
            #pragma unroll
            for (int mt = 0; mt < 2; mt++) {
                int row = m_warp + mt*16 + (lane & 15);
                int ch  = ksub*2 + (lane >> 4);
                ldmx4(afr[mt], aB + row*64 + ((ch ^ ((row>>1)&3))*16));
            }
            uint32_t bfr[4][2];
            #pragma unroll
            for (int np = 0; np < 2; np++) {
                int k  = ksub*16 + ((lane>>3)&1)*8 + (lane&7);
                int cn = (n_warp>>3) + np*2 + (lane>>4);
                uint32_t r[4];
                ldmx4t(r, bB + k*128 + ((cn ^ (k&7))*16));
                bfr[np*2+0][0] = r[0]; bfr[np*2+0][1] = r[1];
                bfr[np*2+1][0] = r[2]; bfr[np*2+1][1] = r[3];
            }
            #pragma unroll
            for (int mt = 0; mt < 2; mt++)
                #pragma unroll
                for (int nt = 0; nt < 4; nt++)
                    mma_bf16(acc[mt][nt], afr[mt], bfr[nt]);
        }
    }

    const int g  = lane >> 2;
    const int tg = lane & 3;
    float* Cf = (float*)Cv;
    bf16*  Cb = (bf16*)Cv;
    #pragma unroll
    for (int mt = 0; mt < 2; mt++) {
        #pragma unroll
        for (int rh = 0; rh < 2; rh++) {
            int m = m0 + m_warp + mt*16 + rh*8 + g;
            long crow = (EPI == EPI_SCATTER_RES) ? (long)win2img(m) : (long)m;
            #pragma unroll
            for (int nt = 0; nt < 4; nt++) {
                int col = n0 + n_warp + nt*8 + tg*2;
                float2 bb = *(const float2*)(bias + col);
                float v0 = acc[mt][nt][rh*2 + 0] + bb.x;
                float v1 = acc[mt][nt][rh*2 + 1] + bb.y;
                if (EPI == EPI_GELU) { v0 = gelu_f(v0); v1 = gelu_f(v1); }
                if (EPI == EPI_RES || EPI == EPI_SCATTER_RES) {
                    float2 r2 = *(const float2*)(resid + crow * N + col);
                    v0 += r2.x; v1 += r2.y;
                }
                if (OUT_BF16) {
                    bf162 o; o.x = __float2bfloat16(v0); o.y = __float2bfloat16(v1);
                    *(bf162*)(Cb + crow * N + col) = o;
                } else {
                    float2 o2 = {v0, v1};
                    *(float2*)(Cf + crow * N + col) = o2;
                }
            }
        }
    }
}

// ---------------- tensor-core windowed attention ----------------
// Block = (window, head), 128 threads (4 warps). Tokens padded 49->64.
// S = Q K^T via mma (K is [n][k] => B col-major, ldmatrix non-trans).
// Softmax in registers (quad shfl). P.V via mma (V is [k][n], ldmatrix trans).
#define BSTR 68   // bias smem row stride (floats): 17 float4, bank phase 4/row

__global__ void __launch_bounds__(128) attn_kernel(const bf16* __restrict__ qkv,
                                                   bf16* __restrict__ out) {
    __shared__ __align__(16) bf16 sq[64*32];
    __shared__ __align__(16) bf16 sk[64*32];
    __shared__ __align__(16) bf16 sv[64*32];
    __shared__ __align__(16) float sbias[64*BSTR];

    const int tid = threadIdx.x, lane = tid & 31, wid = tid >> 5;
    const int win = blockIdx.x, h = blockIdx.y;
    const int w = win & 63;
    const int cls = (((w >> 3) == 7) ? 2 : 0) + (((w & 7) == 7) ? 1 : 0);
    const float* gb = g_bias + ((cls*NH + h) << 12);
    const long base = (long)win * NTOK;
    const float scale = 0.17677669529663687f;

    const uint32_t sqb = (uint32_t)__cvta_generic_to_shared(sq);
    const uint32_t skb = (uint32_t)__cvta_generic_to_shared(sk);
    const uint32_t svb = (uint32_t)__cvta_generic_to_shared(sv);

    // ---- load q/k/v tiles (zero pad rows >= 49), swizzled like GEMM A path
    #pragma unroll
    for (int i = 0; i < 2; i++) {
        int idx = tid + i*128;          // 256 chunks of 16B per tensor
        int n = idx >> 2, ch = idx & 3;
        uint4 zq = {0,0,0,0}, zk = {0,0,0,0}, zv = {0,0,0,0};
        if (n < NTOK) {
            const bf16* p = qkv + (base + n)*(3*CC) + h*HD + ch*8;
            zq = *(const uint4*)(p);
            zk = *(const uint4*)(p + CC);
            zv = *(const uint4*)(p + 2*CC);
        }
        uint32_t off = n*64 + ((ch ^ ((n>>1)&3))*16);
        *(uint4*)((char*)sq + off) = zq;
        *(uint4*)((char*)sk + off) = zk;
        *(uint4*)((char*)sv + off) = zv;
    }
    // ---- load bias tile to padded smem
    #pragma unroll
    for (int i = 0; i < 8; i++) {
        int idx = tid + i*128;          // 1024 float4
        int row = idx >> 4, c4 = idx & 15;
        *(float4*)&sbias[row*BSTR + c4*4] = *(const float4*)(gb + row*64 + c4*4);
    }
    __syncthreads();

    // ---- S = Q K^T : per warp rows 16*wid..+15, all 64 cols
    float s[8][4];
    #pragma unroll
    for (int i = 0; i < 8; i++)
        #pragma unroll
        for (int j = 0; j < 4; j++) s[i][j] = 0.f;

    #pragma unroll
    for (int ksub = 0; ksub < 2; ksub++) {
        uint32_t a[4];
        {
            int row = wid*16 + (lane & 15);
            int ch  = ksub*2 + (lane >> 4);
            ldmx4(a, sqb + row*64 + ((ch ^ ((row>>1)&3))*16));
        }
        #pragma unroll
        for (int bt = 0; bt < 4; bt++) {
            int n  = bt*16 + ((lane>>4)&1)*8 + (lane & 7);
            int ch = ksub*2 + ((lane>>3)&1);
            uint32_t r[4];
            ldmx4(r, skb + n*64 + ((ch ^ ((n>>1)&3))*16));
            uint32_t b0[2] = {r[0], r[1]}, b1[2] = {r[2], r[3]};
            mma_bf16(s[bt*2+0], a, b0);
            mma_bf16(s[bt*2+1], a, b1);
        }
    }

    // ---- scale + bias + softmax (rows r0, r1 per thread)
    const int g  = lane >> 2, tg = lane & 3;
    const int r0 = wid*16 + g, r1 = r0 + 8;
    float mx0 = -1e30f, mx1 = -1e30f;
    #pragma unroll
    for (int nt = 0; nt < 8; nt++) {
        float2 b0 = *(const float2*)&sbias[r0*BSTR + nt*8 + tg*2];
        float2 b1 = *(const float2*)&sbias[r1*BSTR + nt*8 + tg*2];
        s[nt][0] = fmaf(s[nt][0], scale, b0.x);
        s[nt][1] = fmaf(s[nt][1], scale, b0.y);
        s[nt][2] = fmaf(s[nt][2], scale, b1.x);
        s[nt][3] = fmaf(s[nt][3], scale, b1.y);
        mx0 = fmaxf(mx0, fmaxf(s[nt][0], s[nt][1]));
        mx1 = fmaxf(mx1, fmaxf(s[nt][2], s[nt][3]));
    }
    mx0 = fmaxf(mx0, __shfl_xor_sync(~0u, mx0, 1));
    mx0 = fmaxf(mx0, __shfl_xor_sync(~0u, mx0, 2));
    mx1 = fmaxf(mx1, __shfl_xor_sync(~0u, mx1, 1));
    mx1 = fmaxf(mx1, __shfl_xor_sync(~0u, mx1, 2));
    float sum0 = 0.f, sum1 = 0.f;
    #pragma unroll
    for (int nt = 0; nt < 8; nt++) {
        s[nt][0] = __expf(s[nt][0] - mx0);
        s[nt][1] = __expf(s[nt][1] - mx0);
        s[nt][2] = __expf(s[nt][2] - mx1);
        s[nt][3] = __expf(s[nt][3] - mx1);
        sum0 += s[nt][0] + s[nt][1];
        sum1 += s[nt][2] + s[nt][3];
    }
    sum0 += __shfl_xor_sync(~0u, sum0, 1);
    sum0 += __shfl_xor_sync(~0u, sum0, 2);
    sum1 += __shfl_xor_sync(~0u, sum1, 1);
    sum1 += __shfl_xor_sync(~0u, sum1, 2);
    const float inv0 = 1.f / sum0, inv1 = 1.f / sum1;

    // ---- pack P into A fragments (C-frag == A-frag identity)
    uint32_t pk[4][4];
    #pragma unroll
    for (int kt = 0; kt < 4; kt++) {
        pk[kt][0] = packbf(s[2*kt  ][0], s[2*kt  ][1]);
        pk[kt][1] = packbf(s[2*kt  ][2], s[2*kt  ][3]);
        pk[kt][2] = packbf(s[2*kt+1][0], s[2*kt+1][1]);
        pk[kt][3] = packbf(s[2*kt+1][2], s[2*kt+1][3]);
    }

    // ---- O = P V : K=64 tokens (4 k16 steps), N=32 channels (4 n8 tiles)
    float o[4][4];
    #pragma unroll
    for (int i = 0; i < 4; i++)
        #pragma unroll
        for (int j = 0; j < 4; j++) o[i][j] = 0.f;

    #pragma unroll
    for (int kt = 0; kt < 4; kt++) {
        #pragma unroll
        for (int pr = 0; pr < 2; pr++) {
            int k  = kt*16 + ((lane>>3)&1)*8 + (lane & 7);
            int cn = pr*2 + ((lane>>4)&1);
            uint32_t r[4];
            ldmx4t(r, svb + k*64 + ((cn ^ ((k>>1)&3))*16));
            uint32_t b0[2] = {r[0], r[1]}, b1[2] = {r[2], r[3]};
            mma_bf16(o[pr*2+0], pk[kt], b0);
            mma_bf16(o[pr*2+1], pk[kt], b1);
        }
    }

    // ---- store (rows < 49), normalization folded in
    #pragma unroll
    for (int nt = 0; nt < 4; nt++) {
        int col = h*HD + nt*8 + tg*2;
        if (r0 < NTOK) {
            bf162 t; t.x = __float2bfloat16(o[nt][0]*inv0); t.y = __float2bfloat16(o[nt][1]*inv0);
            *(bf162*)(out + (base + r0)*CC + col) = t;
        }
        if (r1 < NTOK) {
            bf162 t; t.x = __float2bfloat16(o[nt][2]*inv1); t.y = __float2bfloat16(o[nt][3]*inv1);
            *(bf162*)(out + (base + r1)*CC + col) = t;
        }
    }
}

// ---------------- launch ----------------
extern "C" void kernel_launch(void* const* d_in, const int* in_sizes, int n_in,
                              void* d_out, int out_size) {
    const float* x       = (const float*)d_in[0];
    const float* n1g     = (const float*)d_in[1];
    const float* n1b     = (const float*)d_in[2];
    const float* qkv_w   = (const float*)d_in[3];
    const float* qkv_b   = (const float*)d_in[4];
    const float* rpb     = (const float*)d_in[5];
    const float* proj_w  = (const float*)d_in[6];
    const float* proj_b  = (const float*)d_in[7];
    const float* n2g     = (const float*)d_in[8];
    const float* n2b     = (const float*)d_in[9];
    const float* fc1_w   = (const float*)d_in[10];
    const float* fc1_b   = (const float*)d_in[11];
    const float* fc2_w   = (const float*)d_in[12];
    const float* fc2_b   = (const float*)d_in[13];
    float* out = (float*)d_out;

    bf16 *xn, *qkv, *attn, *xn2, *hbuf, *wq, *wp, *w1, *w2;
    float *y;
    cudaGetSymbolAddress((void**)&xn,   g_xn_h);
    cudaGetSymbolAddress((void**)&qkv,  g_qkv_h);
    cudaGetSymbolAddress((void**)&attn, g_attn_h);
    cudaGetSymbolAddress((void**)&y,    g_y);
    cudaGetSymbolAddress((void**)&xn2,  g_xn2_h);
    cudaGetSymbolAddress((void**)&hbuf, g_h_h);
    cudaGetSymbolAddress((void**)&wq,   g_wq);
    cudaGetSymbolAddress((void**)&wp,   g_wp);
    cudaGetSymbolAddress((void**)&w1,   g_w1);
    cudaGetSymbolAddress((void**)&w2,   g_w2);

    f2bf_all<<<(WTOT+255)/256, 256>>>(qkv_w, proj_w, fc1_w, fc2_w, wq, wp, w1, w2);
    bias_precompute<<<(4*NH*4096)/256, 256>>>(rpb);

    const int mblk = MROWS / BM;   // 784

    ln_kernel<<<MROWS/8, 256>>>(x, n1g, n1b, xn);
    tgemm<EPI_NONE, true, true><<<dim3(3*CC/BN, mblk), 256>>>(xn, wq, qkv_b, qkv, nullptr, 3*CC, CC);
    attn_kernel<<<dim3(BATCH*NWIN, NH), 128>>>(qkv, attn);
    tgemm<EPI_SCATTER_RES, false, false><<<dim3(CC/BN, mblk), 256>>>(attn, wp, proj_b, y, x, CC, CC);
    ln_kernel<<<MROWS/8, 256>>>(y, n2g, n2b, xn2);
    tgemm<EPI_GELU, false, true><<<dim3(HID/BN, mblk), 256>>>(xn2, w1, fc1_b, hbuf, nullptr, HID, CC);
    tgemm<EPI_RES, false, false><<<dim3(CC/BN, mblk), 256>>>(hbuf, w2, fc2_b, out, y, CC, HID);
}

// round 9
// speedup vs baseline: 5.9638x; 1.0203x over previous
// R9: 3-stage cp.async ring in tgemm (2 loads in flight, wait_group 1).
// Attention/LN/epilogues unchanged from R8 (verified).
#include <cuda_runtime.h>
#include <cuda_bf16.h>
#include <math.h>
#include <stdint.h>

#define BATCH 32
#define HH 56
#define WW2 56
#define CC 192
#define HID 768
#define WS 7
#define SS 3
#define NH 6
#define HD 32
#define NTOK 49
#define NWIN 64
#define MROWS (BATCH*HH*WW2)        // 100352
#define ROWS_PER_BATCH (NWIN*NTOK)  // 3136

typedef __nv_bfloat16 bf16;
typedef __nv_bfloat162 bf162;

// ---------------- scratch ----------------
__device__ bf16  g_xn_h [MROWS*CC];
__device__ bf16  g_qkv_h[(long)MROWS*3*CC];
__device__ bf16  g_attn_h[MROWS*CC];
__device__ float g_y    [MROWS*CC];
__device__ bf16  g_xn2_h[MROWS*CC];
__device__ bf16  g_h_h  [(long)MROWS*HID];
__device__ bf16  g_wq[CC*3*CC];
__device__ bf16  g_wp[CC*CC];
__device__ bf16  g_w1[CC*HID];
__device__ bf16  g_w2[HID*CC];
__device__ float g_bias[4*NH*64*64];    // [class][head][64][64]

__device__ __forceinline__ int win2img(int r) {
    int b   = r / ROWS_PER_BATCH;
    int rem = r - b * ROWS_PER_BATCH;
    int w   = rem / NTOK;
    int n   = rem - w * NTOK;
    int i = n / WS, j = n - WS * (n / WS);
    int hs = (w >> 3) * WS + i;
    int ws = (w & 7) * WS + j;
    int h  = hs + SS; if (h  >= HH)  h  -= HH;
    int wc = ws + SS; if (wc >= WW2) wc -= WW2;
    return (b * HH + h) * WW2 + wc;
}

// ---------------- fp32 -> bf16 conversion for all four weights ------------
#define WQ_N (CC*3*CC)
#define WP_N (CC*CC)
#define W1_N (CC*HID)
#define W2_N (HID*CC)
#define WTOT (WQ_N+WP_N+W1_N+W2_N)
__global__ void f2bf_all(const float* __restrict__ s0, const float* __restrict__ s1,
                         const float* __restrict__ s2, const float* __restrict__ s3,
                         bf16* d0, bf16* d1, bf16* d2, bf16* d3) {
    int i = blockIdx.x * 256 + threadIdx.x;
    if (i < WQ_N) { d0[i] = __float2bfloat16(s0[i]); return; }
    i -= WQ_N;
    if (i < WP_N) { d1[i] = __float2bfloat16(s1[i]); return; }
    i -= WP_N;
    if (i < W1_N) { d2[i] = __float2bfloat16(s2[i]); return; }
    i -= W1_N;
    if (i < W2_N) { d3[i] = __float2bfloat16(s3[i]); }
}

// ---------------- attention bias table: [class][head][64][64] -------------
__global__ void bias_precompute(const float* __restrict__ rpb) {
    int idx = blockIdx.x * 256 + threadIdx.x;   // 4*6*4096 total
    int cls = idx / (NH*4096);
    int rem = idx - cls*NH*4096;
    int h   = rem >> 12;
    int p   = rem & 4095;
    int n = p >> 6, m = p & 63;
    float v;
    if (m >= NTOK) v = -1e9f;
    else if (n >= NTOK) v = 0.f;
    else {
        int in_ = n / WS, jn = n % WS, im = m / WS, jm = m % WS;
        v = rpb[((in_-im+6)*13 + (jn-jm+6))*NH + h];
        int rE = cls >> 1, cE = cls & 1;
        int rn = rE ? (in_ < 4 ? 1 : 2) : 0;
        int cn = cE ? (jn  < 4 ? 1 : 2) : 0;
        int rm = rE ? (im  < 4 ? 1 : 2) : 0;
        int cm = cE ? (jm  < 4 ? 1 : 2) : 0;
        if (rn*3+cn != rm*3+cm) v -= 100.f;
    }
    g_bias[idx] = v;
}

// ---------------- LayerNorm: warp per row, bf16 out ----------------
__global__ void ln_kernel(const float* __restrict__ x, const float* __restrict__ g,
                          const float* __restrict__ b, bf16* __restrict__ o) {
    int row  = blockIdx.x * 8 + (threadIdx.x >> 5);
    int lane = threadIdx.x & 31;
    const float* p = x + (long)row * CC;
    float v[6];
    float s = 0.f;
    #pragma unroll
    for (int i = 0; i < 6; i++) { v[i] = p[lane + 32*i]; s += v[i]; }
    #pragma unroll
    for (int off = 16; off; off >>= 1) s += __shfl_xor_sync(~0u, s, off);
    float mu = s * (1.f/192.f);
    float vs = 0.f;
    #pragma unroll
    for (int i = 0; i < 6; i++) { float d = v[i]-mu; vs += d*d; }
    #pragma unroll
    for (int off = 16; off; off >>= 1) vs += __shfl_xor_sync(~0u, vs, off);
    float r = rsqrtf(vs * (1.f/192.f) + 1e-5f);
    bf16* op = o + (long)row * CC;
    #pragma unroll
    for (int i = 0; i < 6; i++) {
        int c = lane + 32*i;
        op[c] = __float2bfloat16((v[i]-mu) * r * g[c] + b[c]);
    }
}

// ---------------- bf16 mma helpers ----------------
__device__ __forceinline__ void mma_bf16(float* c, const uint32_t* a, const uint32_t* b) {
    asm volatile("mma.sync.aligned.m16n8k16.row.col.f32.bf16.bf16.f32 "
        "{%0,%1,%2,%3},{%4,%5,%6,%7},{%8,%9},{%0,%1,%2,%3};"
        : "+f"(c[0]), "+f"(c[1]), "+f"(c[2]), "+f"(c[3])
        : "r"(a[0]), "r"(a[1]), "r"(a[2]), "r"(a[3]), "r"(b[0]), "r"(b[1]));
}
__device__ __forceinline__ void ldmx4(uint32_t* r, uint32_t addr) {
    asm volatile("ldmatrix.sync.aligned.m8n8.x4.shared.b16 {%0,%1,%2,%3}, [%4];"
        : "=r"(r[0]), "=r"(r[1]), "=r"(r[2]), "=r"(r[3]) : "r"(addr));
}
__device__ __forceinline__ void ldmx4t(uint32_t* r, uint32_t addr) {
    asm volatile("ldmatrix.sync.aligned.m8n8.x4.trans.shared.b16 {%0,%1,%2,%3}, [%4];"
        : "=r"(r[0]), "=r"(r[1]), "=r"(r[2]), "=r"(r[3]) : "r"(addr));
}
__device__ __forceinline__ void cp16(uint32_t smem, const void* g) {
    asm volatile("cp.async.cg.shared.global [%0], [%1], 16;" :: "r"(smem), "l"(g));
}
__device__ __forceinline__ uint32_t packbf(float lo, float hi) {
    bf162 t; t.x = __float2bfloat16(lo); t.y = __float2bfloat16(hi);
    return *(uint32_t*)&t;
}

// ---------------- bf16 tensor-core GEMM, 3-stage cp.async ring ------------
#define BM 128
#define BN 64
#define BK 32
#define A_BYTES (BM*64)
#define B_BYTES (BK*128)
#define NSTAGE 3

enum { EPI_NONE = 0, EPI_GELU = 1, EPI_RES = 2, EPI_SCATTER_RES = 3 };

__device__ __forceinline__ float gelu_f(float x) {
    return 0.5f * x * (1.0f + erff(x * 0.70710678118654752f));
}

template<int EPI, bool GATHER_A, bool OUT_BF16>
__global__ void __launch_bounds__(256) tgemm(const bf16* __restrict__ A,
                                             const bf16* __restrict__ Bm,
                                             const float* __restrict__ bias,
                                             void* __restrict__ Cv,
                                             const float* __restrict__ resid,
                                             int N, int K) {
    __shared__ char smemA[NSTAGE*A_BYTES];
    __shared__ char smemB[NSTAGE*B_BYTES];
    const uint32_t sA = (uint32_t)__cvta_generic_to_shared(smemA);
    const uint32_t sB = (uint32_t)__cvta_generic_to_shared(smemB);
    const int tid = threadIdx.x, lane = tid & 31, warp = tid >> 5;
    const int m0 = blockIdx.y * BM;
    const int n0 = blockIdx.x * BN;

    const int arow = tid >> 1;
    const int ac0  = (tid & 1) * 2;
    const int aswr = (arow >> 1) & 3;
    const bf16* agp = A + (long)(GATHER_A ? win2img(m0 + arow) : (m0 + arow)) * K + (tid & 1) * 16;
    const uint32_t adst0 = arow*64 + (uint32_t)(((ac0+0) ^ aswr)*16);
    const uint32_t adst1 = arow*64 + (uint32_t)(((ac0+1) ^ aswr)*16);

    const int bk = tid >> 3;
    const int bc = tid & 7;
    const bf16* bgp = Bm + (long)bk * N + n0 + bc * 8;
    const uint32_t bdst = bk*128 + (uint32_t)((bc ^ (bk & 7))*16);

    const int m_warp = (warp & 3) * 32;
    const int n_warp = (warp >> 2) * 32;

    float acc[2][4][4];
    #pragma unroll
    for (int i = 0; i < 2; i++)
        #pragma unroll
        for (int j = 0; j < 4; j++)
            #pragma unroll
            for (int l = 0; l < 4; l++) acc[i][j][l] = 0.f;

    const int nk = K / BK;    // >= 6 for all call sites

    // prologue: stages 0 and 1 in flight
    #pragma unroll
    for (int s = 0; s < 2; s++) {
        cp16(sA + s*A_BYTES + adst0, agp + s*BK);
        cp16(sA + s*A_BYTES + adst1, agp + s*BK + 8);
        cp16(sB + s*B_BYTES + bdst,  bgp + (long)s*BK*N);
        asm volatile("cp.async.commit_group;" ::: "memory");
    }

    int buf = 0;   // stage it lives in buffer (it % 3)
    for (int it = 0; it < nk; ++it) {
        // stage it ready when <=1 group pending (stage it+1 may still fly)
        if (it + 1 < nk) asm volatile("cp.async.wait_group 1;" ::: "memory");
        else             asm volatile("cp.async.wait_group 0;" ::: "memory");
        __syncthreads();
        // issue stage it+2 into buffer (it+2)%3 == (it-1)%3: all warps are past
        // compute it-1 because of the barrier above.
        if (it + 2 < nk) {
            int nb = buf + 2; if (nb >= NSTAGE) nb -= NSTAGE;
            const bf16* ag = agp + (it + 2) * BK;
            const bf16* bg = bgp + (long)(it + 2) * BK * N;
            cp16(sA + nb*A_BYTES + adst0, ag);
            cp16(sA + nb*A_BYTES + adst1, ag + 8);
            cp16(sB + nb*B_BYTES + bdst,  bg);
            asm volatile("cp.async.commit_group;" ::: "memory");
        }

        const uint32_t aB = sA + buf*A_BYTES;
        const uint32_t bB = sB + buf*B_BYTES;
        #pragma unroll
        for (int ksub = 0; ksub < 2; ksub++) {
            uint32_t afr[2][4];
            #pragma unroll
            for (int mt = 0; mt < 2; mt++) {
                int row = m_warp + mt*16 + (lane & 15);
                int ch  = ksub*2 + (lane >> 4);
                ldmx4(afr[mt], aB + row*64 + ((ch ^ ((row>>1)&3))*16));
            }
            uint32_t bfr[4][2];
            #pragma unroll
            for (int np = 0; np < 2; np++) {
                int k  = ksub*16 + ((lane>>3)&1)*8 + (lane&7);
                int cn = (n_warp>>3) + np*2 + (lane>>4);
                uint32_t r[4];
                ldmx4t(r, bB + k*128 + ((cn ^ (k&7))*16));
                bfr[np*2+0][0] = r[0]; bfr[np*2+0][1] = r[1];
                bfr[np*2+1][0] = r[2]; bfr[np*2+1][1] = r[3];
            }
            #pragma unroll
            for (int mt = 0; mt < 2; mt++)
                #pragma unroll
                for (int nt = 0; nt < 4; nt++)
                    mma_bf16(acc[mt][nt], afr[mt], bfr[nt]);
        }
        if (++buf == NSTAGE) buf = 0;
    }

    const int g  = lane >> 2;
    const int tg = lane & 3;
    float* Cf = (float*)Cv;
    bf16*  Cb = (bf16*)Cv;
    #pragma unroll
    for (int mt = 0; mt < 2; mt++) {
        #pragma unroll
        for (int rh = 0; rh < 2; rh++) {
            int m = m0 + m_warp + mt*16 + rh*8 + g;
            long crow = (EPI == EPI_SCATTER_RES) ? (long)win2img(m) : (long)m;
            #pragma unroll
            for (int nt = 0; nt < 4; nt++) {
                int col = n0 + n_warp + nt*8 + tg*2;
                float2 bb = *(const float2*)(bias + col);
                float v0 = acc[mt][nt][rh*2 + 0] + bb.x;
                float v1 = acc[mt][nt][rh*2 + 1] + bb.y;
                if (EPI == EPI_GELU) { v0 = gelu_f(v0); v1 = gelu_f(v1); }
                if (EPI == EPI_RES || EPI == EPI_SCATTER_RES) {
                    float2 r2 = *(const float2*)(resid + crow * N + col);
                    v0 += r2.x; v1 += r2.y;
                }
                if (OUT_BF16) {
                    bf162 o; o.x = __float2bfloat16(v0); o.y = __float2bfloat16(v1);
                    *(bf162*)(Cb + crow * N + col) = o;
                } else {
                    float2 o2 = {v0, v1};
                    *(float2*)(Cf + crow * N + col) = o2;
                }
            }
        }
    }
}

// ---------------- tensor-core windowed attention (unchanged) --------------
#define BSTR 68

__global__ void __launch_bounds__(128) attn_kernel(const bf16* __restrict__ qkv,
                                                   bf16* __restrict__ out) {
    __shared__ __align__(16) bf16 sq[64*32];
    __shared__ __align__(16) bf16 sk[64*32];
    __shared__ __align__(16) bf16 sv[64*32];
    __shared__ __align__(16) float sbias[64*BSTR];

    const int tid = threadIdx.x, lane = tid & 31, wid = tid >> 5;
    const int win = blockIdx.x, h = blockIdx.y;
    const int w = win & 63;
    const int cls = (((w >> 3) == 7) ? 2 : 0) + (((w & 7) == 7) ? 1 : 0);
    const float* gb = g_bias + ((cls*NH + h) << 12);
    const long base = (long)win * NTOK;
    const float scale = 0.17677669529663687f;

    const uint32_t sqb = (uint32_t)__cvta_generic_to_shared(sq);
    const uint32_t skb = (uint32_t)__cvta_generic_to_shared(sk);
    const uint32_t svb = (uint32_t)__cvta_generic_to_shared(sv);

    #pragma unroll
    for (int i = 0; i < 2; i++) {
        int idx = tid + i*128;
        int n = idx >> 2, ch = idx & 3;
        uint4 zq = {0,0,0,0}, zk = {0,0,0,0}, zv = {0,0,0,0};
        if (n < NTOK) {
            const bf16* p = qkv + (base + n)*(3*CC) + h*HD + ch*8;
            zq = *(const uint4*)(p);
            zk = *(const uint4*)(p + CC);
            zv = *(const uint4*)(p + 2*CC);
        }
        uint32_t off = n*64 + ((ch ^ ((n>>1)&3))*16);
        *(uint4*)((char*)sq + off) = zq;
        *(uint4*)((char*)sk + off) = zk;
        *(uint4*)((char*)sv + off) = zv;
    }
    #pragma unroll
    for (int i = 0; i < 8; i++) {
        int idx = tid + i*128;
        int row = idx >> 4, c4 = idx & 15;
        *(float4*)&sbias[row*BSTR + c4*4] = *(const float4*)(gb + row*64 + c4*4);
    }
    __syncthreads();

    float s[8][4];
    #pragma unroll
    for (int i = 0; i < 8; i++)
        #pragma unroll
        for (int j = 0; j < 4; j++) s[i][j] = 0.f;

    #pragma unroll
    for (int ksub = 0; ksub < 2; ksub++) {
        uint32_t a[4];
        {
            int row = wid*16 + (lane & 15);
            int ch  = ksub*2 + (lane >> 4);
            ldmx4(a, sqb + row*64 + ((ch ^ ((row>>1)&3))*16));
        }
        #pragma unroll
        for (int bt = 0; bt < 4; bt++) {
            int n  = bt*16 + ((lane>>4)&1)*8 + (lane & 7);
            int ch = ksub*2 + ((lane>>3)&1);
            uint32_t r[4];
            ldmx4(r, skb + n*64 + ((ch ^ ((n>>1)&3))*16));
            uint32_t b0[2] = {r[0], r[1]}, b1[2] = {r[2], r[3]};
            mma_bf16(s[bt*2+0], a, b0);
            mma_bf16(s[bt*2+1], a, b1);
        }
    }

    const int g  = lane >> 2, tg = lane & 3;
    const int r0 = wid*16 + g, r1 = r0 + 8;
    float mx0 = -1e30f, mx1 = -1e30f;
    #pragma unroll
    for (int nt = 0; nt < 8; nt++) {
        float2 b0 = *(const float2*)&sbias[r0*BSTR + nt*8 + tg*2];
        float2 b1 = *(const float2*)&sbias[r1*BSTR + nt*8 + tg*2];
        s[nt][0] = fmaf(s[nt][0], scale, b0.x);
        s[nt][1] = fmaf(s[nt][1], scale, b0.y);
        s[nt][2] = fmaf(s[nt][2], scale, b1.x);
        s[nt][3] = fmaf(s[nt][3], scale, b1.y);
        mx0 = fmaxf(mx0, fmaxf(s[nt][0], s[nt][1]));
        mx1 = fmaxf(mx1, fmaxf(s[nt][2], s[nt][3]));
    }
    mx0 = fmaxf(mx0, __shfl_xor_sync(~0u, mx0, 1));
    mx0 = fmaxf(mx0, __shfl_xor_sync(~0u, mx0, 2));
    mx1 = fmaxf(mx1, __shfl_xor_sync(~0u, mx1, 1));
    mx1 = fmaxf(mx1, __shfl_xor_sync(~0u, mx1, 2));
    float sum0 = 0.f, sum1 = 0.f;
    #pragma unroll
    for (int nt = 0; nt < 8; nt++) {
        s[nt][0] = __expf(s[nt][0] - mx0);
        s[nt][1] = __expf(s[nt][1] - mx0);
        s[nt][2] = __expf(s[nt][2] - mx1);
        s[nt][3] = __expf(s[nt][3] - mx1);
        sum0 += s[nt][0] + s[nt][1];
        sum1 += s[nt][2] + s[nt][3];
    }
    sum0 += __shfl_xor_sync(~0u, sum0, 1);
    sum0 += __shfl_xor_sync(~0u, sum0, 2);
    sum1 += __shfl_xor_sync(~0u, sum1, 1);
    sum1 += __shfl_xor_sync(~0u, sum1, 2);
    const float inv0 = 1.f / sum0, inv1 = 1.f / sum1;

    uint32_t pk[4][4];
    #pragma unroll
    for (int kt = 0; kt < 4; kt++) {
        pk[kt][0] = packbf(s[2*kt  ][0], s[2*kt  ][1]);
        pk[kt][1] = packbf(s[2*kt  ][2], s[2*kt  ][3]);
        pk[kt][2] = packbf(s[2*kt+1][0], s[2*kt+1][1]);
        pk[kt][3] = packbf(s[2*kt+1][2], s[2*kt+1][3]);
    }

    float o[4][4];
    #pragma unroll
    for (int i = 0; i < 4; i++)
        #pragma unroll
        for (int j = 0; j < 4; j++) o[i][j] = 0.f;

    #pragma unroll
    for (int kt = 0; kt < 4; kt++) {
        #pragma unroll
        for (int pr = 0; pr < 2; pr++) {
            int k  = kt*16 + ((lane>>3)&1)*8 + (lane & 7);
            int cn = pr*2 + ((lane>>4)&1);
            uint32_t r[4];
            ldmx4t(r, svb + k*64 + ((cn ^ ((k>>1)&3))*16));
            uint32_t b0[2] = {r[0], r[1]}, b1[2] = {r[2], r[3]};
            mma_bf16(o[pr*2+0], pk[kt], b0);
            mma_bf16(o[pr*2+1], pk[kt], b1);
        }
    }

    #pragma unroll
    for (int nt = 0; nt < 4; nt++) {
        int col = h*HD + nt*8 + tg*2;
        if (r0 < NTOK) {
            bf162 t; t.x = __float2bfloat16(o[nt][0]*inv0); t.y = __float2bfloat16(o[nt][1]*inv0);
            *(bf162*)(out + (base + r0)*CC + col) = t;
        }
        if (r1 < NTOK) {
            bf162 t; t.x = __float2bfloat16(o[nt][2]*inv1); t.y = __float2bfloat16(o[nt][3]*inv1);
            *(bf162*)(out + (base + r1)*CC + col) = t;
        }
    }
}

// ---------------- launch ----------------
extern "C" void kernel_launch(void* const* d_in, const int* in_sizes, int n_in,
                              void* d_out, int out_size) {
    const float* x       = (const float*)d_in[0];
    const float* n1g     = (const float*)d_in[1];
    const float* n1b     = (const float*)d_in[2];
    const float* qkv_w   = (const float*)d_in[3];
    const float* qkv_b   = (const float*)d_in[4];
    const float* rpb     = (const float*)d_in[5];
    const float* proj_w  = (const float*)d_in[6];
    const float* proj_b  = (const float*)d_in[7];
    const float* n2g     = (const float*)d_in[8];
    const float* n2b     = (const float*)d_in[9];
    const float* fc1_w   = (const float*)d_in[10];
    const float* fc1_b   = (const float*)d_in[11];
    const float* fc2_w   = (const float*)d_in[12];
    const float* fc2_b   = (const float*)d_in[13];
    float* out = (float*)d_out;

    bf16 *xn, *qkv, *attn, *xn2, *hbuf, *wq, *wp, *w1, *w2;
    float *y;
    cudaGetSymbolAddress((void**)&xn,   g_xn_h);
    cudaGetSymbolAddress((void**)&qkv,  g_qkv_h);
    cudaGetSymbolAddress((void**)&attn, g_attn_h);
    cudaGetSymbolAddress((void**)&y,    g_y);
    cudaGetSymbolAddress((void**)&xn2,  g_xn2_h);
    cudaGetSymbolAddress((void**)&hbuf, g_h_h);
    cudaGetSymbolAddress((void**)&wq,   g_wq);
    cudaGetSymbolAddress((void**)&wp,   g_wp);
    cudaGetSymbolAddress((void**)&w1,   g_w1);
    cudaGetSymbolAddress((void**)&w2,   g_w2);

    f2bf_all<<<(WTOT+255)/256, 256>>>(qkv_w, proj_w, fc1_w, fc2_w, wq, wp, w1, w2);
    bias_precompute<<<(4*NH*4096)/256, 256>>>(rpb);

    const int mblk = MROWS / BM;   // 784

    ln_kernel<<<MROWS/8, 256>>>(x, n1g, n1b, xn);
    tgemm<EPI_NONE, true, true><<<dim3(3*CC/BN, mblk), 256>>>(xn, wq, qkv_b, qkv, nullptr, 3*CC, CC);
    attn_kernel<<<dim3(BATCH*NWIN, NH), 128>>>(qkv, attn);
    tgemm<EPI_SCATTER_RES, false, false><<<dim3(CC/BN, mblk), 256>>>(attn, wp, proj_b, y, x, CC, CC);
    ln_kernel<<<MROWS/8, 256>>>(y, n2g, n2b, xn2);
    tgemm<EPI_GELU, false, true><<<dim3(HID/BN, mblk), 256>>>(xn2, w1, fc1_b, hbuf, nullptr, HID, CC);
    tgemm<EPI_RES, false, false><<<dim3(CC/BN, mblk), 256>>>(hbuf, w2, fc2_b, out, y, CC, HID);
}

// round 11
// speedup vs baseline: 6.1728x; 1.0350x over previous
// R11: mma.sync GEMM restructured — 4 warps x (32x64) warp tiles, 25% fewer
// ldmatrix per output + 2x mma ILP per fragment. (tcgen05 rejected: harness
// targets sm_100 base, not sm_100a.) Attention/LN unchanged from R9.
#include <cuda_runtime.h>
#include <cuda_bf16.h>
#include <math.h>
#include <stdint.h>

#define BATCH 32
#define HH 56
#define WW2 56
#define CC 192
#define HID 768
#define WS 7
#define SS 3
#define NH 6
#define HD 32
#define NTOK 49
#define NWIN 64
#define MROWS (BATCH*HH*WW2)
#define ROWS_PER_BATCH (NWIN*NTOK)

typedef __nv_bfloat16 bf16;
typedef __nv_bfloat162 bf162;

// ---------------- scratch ----------------
__device__ bf16  g_xn_h [MROWS*CC];
__device__ bf16  g_qkv_h[(long)MROWS*3*CC];
__device__ bf16  g_attn_h[MROWS*CC];
__device__ float g_y    [MROWS*CC];
__device__ bf16  g_xn2_h[MROWS*CC];
__device__ bf16  g_h_h  [(long)MROWS*HID];
__device__ bf16  g_wq[CC*3*CC];
__device__ bf16  g_wp[CC*CC];
__device__ bf16  g_w1[CC*HID];
__device__ bf16  g_w2[HID*CC];
__device__ float g_bias[4*NH*64*64];

__device__ __forceinline__ int win2img(int r) {
    int b   = r / ROWS_PER_BATCH;
    int rem = r - b * ROWS_PER_BATCH;
    int w   = rem / NTOK;
    int n   = rem - w * NTOK;
    int i = n / WS, j = n - WS * (n / WS);
    int hs = (w >> 3) * WS + i;
    int ws = (w & 7) * WS + j;
    int h  = hs + SS; if (h  >= HH)  h  -= HH;
    int wc = ws + SS; if (wc >= WW2) wc -= WW2;
    return (b * HH + h) * WW2 + wc;
}

// ---------------- fp32 -> bf16 conversion for all four weights ------------
#define WQ_N (CC*3*CC)
#define WP_N (CC*CC)
#define W1_N (CC*HID)
#define W2_N (HID*CC)
#define WTOT (WQ_N+WP_N+W1_N+W2_N)
__global__ void f2bf_all(const float* __restrict__ s0, const float* __restrict__ s1,
                         const float* __restrict__ s2, const float* __restrict__ s3,
                         bf16* d0, bf16* d1, bf16* d2, bf16* d3) {
    int i = blockIdx.x * 256 + threadIdx.x;
    if (i < WQ_N) { d0[i] = __float2bfloat16(s0[i]); return; }
    i -= WQ_N;
    if (i < WP_N) { d1[i] = __float2bfloat16(s1[i]); return; }
    i -= WP_N;
    if (i < W1_N) { d2[i] = __float2bfloat16(s2[i]); return; }
    i -= W1_N;
    if (i < W2_N) { d3[i] = __float2bfloat16(s3[i]); }
}

// ---------------- attention bias table ----------------
__global__ void bias_precompute(const float* __restrict__ rpb) {
    int idx = blockIdx.x * 256 + threadIdx.x;
    int cls = idx / (NH*4096);
    int rem = idx - cls*NH*4096;
    int h   = rem >> 12;
    int p   = rem & 4095;
    int n = p >> 6, m = p & 63;
    float v;
    if (m >= NTOK) v = -1e9f;
    else if (n >= NTOK) v = 0.f;
    else {
        int in_ = n / WS, jn = n % WS, im = m / WS, jm = m % WS;
        v = rpb[((in_-im+6)*13 + (jn-jm+6))*NH + h];
        int rE = cls >> 1, cE = cls & 1;
        int rn = rE ? (in_ < 4 ? 1 : 2) : 0;
        int cn = cE ? (jn  < 4 ? 1 : 2) : 0;
        int rm = rE ? (im  < 4 ? 1 : 2) : 0;
        int cm = cE ? (jm  < 4 ? 1 : 2) : 0;
        if (rn*3+cn != rm*3+cm) v -= 100.f;
    }
    g_bias[idx] = v;
}

// ---------------- LayerNorm ----------------
__global__ void ln_kernel(const float* __restrict__ x, const float* __restrict__ g,
                          const float* __restrict__ b, bf16* __restrict__ o) {
    int row  = blockIdx.x * 8 + (threadIdx.x >> 5);
    int lane = threadIdx.x & 31;
    const float* p = x + (long)row * CC;
    float v[6];
    float s = 0.f;
    #pragma unroll
    for (int i = 0; i < 6; i++) { v[i] = p[lane + 32*i]; s += v[i]; }
    #pragma unroll
    for (int off = 16; off; off >>= 1) s += __shfl_xor_sync(~0u, s, off);
    float mu = s * (1.f/192.f);
    float vs = 0.f;
    #pragma unroll
    for (int i = 0; i < 6; i++) { float d = v[i]-mu; vs += d*d; }
    #pragma unroll
    for (int off = 16; off; off >>= 1) vs += __shfl_xor_sync(~0u, vs, off);
    float r = rsqrtf(vs * (1.f/192.f) + 1e-5f);
    bf16* op = o + (long)row * CC;
    #pragma unroll
    for (int i = 0; i < 6; i++) {
        int c = lane + 32*i;
        op[c] = __float2bfloat16((v[i]-mu) * r * g[c] + b[c]);
    }
}

// ---------------- helpers ----------------
__device__ __forceinline__ void mma_bf16(float* c, const uint32_t* a, const uint32_t* b) {
    asm volatile("mma.sync.aligned.m16n8k16.row.col.f32.bf16.bf16.f32 "
        "{%0,%1,%2,%3},{%4,%5,%6,%7},{%8,%9},{%0,%1,%2,%3};"
        : "+f"(c[0]), "+f"(c[1]), "+f"(c[2]), "+f"(c[3])
        : "r"(a[0]), "r"(a[1]), "r"(a[2]), "r"(a[3]), "r"(b[0]), "r"(b[1]));
}
__device__ __forceinline__ void ldmx4(uint32_t* r, uint32_t addr) {
    asm volatile("ldmatrix.sync.aligned.m8n8.x4.shared.b16 {%0,%1,%2,%3}, [%4];"
        : "=r"(r[0]), "=r"(r[1]), "=r"(r[2]), "=r"(r[3]) : "r"(addr));
}
__device__ __forceinline__ void ldmx4t(uint32_t* r, uint32_t addr) {
    asm volatile("ldmatrix.sync.aligned.m8n8.x4.trans.shared.b16 {%0,%1,%2,%3}, [%4];"
        : "=r"(r[0]), "=r"(r[1]), "=r"(r[2]), "=r"(r[3]) : "r"(addr));
}
__device__ __forceinline__ void cp16(uint32_t smem, const void* g) {
    asm volatile("cp.async.cg.shared.global [%0], [%1], 16;" :: "r"(smem), "l"(g));
}
__device__ __forceinline__ uint32_t packbf(float lo, float hi) {
    bf162 t; t.x = __float2bfloat16(lo); t.y = __float2bfloat16(hi);
    return *(uint32_t*)&t;
}

// ---------------- bf16 mma GEMM: 128x64 tile, 4 warps x (32x64) -----------
#define BM 128
#define BN 64
#define BK 32
#define A_BYTES (BM*64)      // 8192 per stage
#define B_BYTES (BK*128)     // 4096 per stage
#define NSTAGE 3

enum { EPI_NONE = 0, EPI_GELU = 1, EPI_RES = 2, EPI_SCATTER_RES = 3 };

__device__ __forceinline__ float gelu_f(float x) {
    return 0.5f * x * (1.0f + erff(x * 0.70710678118654752f));
}

template<int EPI, bool GATHER_A, bool OUT_BF16>
__global__ void __launch_bounds__(128) tgemm(const bf16* __restrict__ A,
                                             const bf16* __restrict__ Bm,
                                             const float* __restrict__ bias,
                                             void* __restrict__ Cv,
                                             const float* __restrict__ resid,
                                             int N, int K) {
    __shared__ char smemA[NSTAGE*A_BYTES];
    __shared__ char smemB[NSTAGE*B_BYTES];
    const uint32_t sA = (uint32_t)__cvta_generic_to_shared(smemA);
    const uint32_t sB = (uint32_t)__cvta_generic_to_shared(smemB);
    const int tid = threadIdx.x, lane = tid & 31, warp = tid >> 5;
    const int m0 = blockIdx.y * BM;
    const int n0 = blockIdx.x * BN;

    // loads: each thread = virtual threads {tid, tid+128} of the R9 256-map
    // A: vt -> row vt/2, 16-elem half (vt&1), 2 cp16
    const bf16* agp[2];
    uint32_t adst[2][2];
    #pragma unroll
    for (int v = 0; v < 2; v++) {
        int vt = tid + v*128;
        int arow = vt >> 1;
        int ac0  = (vt & 1) * 2;
        int aswr = (arow >> 1) & 3;
        agp[v] = A + (long)(GATHER_A ? win2img(m0 + arow) : (m0 + arow)) * K + (vt & 1) * 16;
        adst[v][0] = arow*64 + (uint32_t)(((ac0+0) ^ aswr)*16);
        adst[v][1] = arow*64 + (uint32_t)(((ac0+1) ^ aswr)*16);
    }
    // B: vt -> k row vt/8, n chunk vt&7, 1 cp16
    const bf16* bgp[2];
    uint32_t bdst[2];
    #pragma unroll
    for (int v = 0; v < 2; v++) {
        int vt = tid + v*128;
        int bk = vt >> 3;
        int bc = vt & 7;
        bgp[v] = Bm + (long)bk * N + n0 + bc * 8;
        bdst[v] = bk*128 + (uint32_t)((bc ^ (bk & 7))*16);
    }

    const int m_warp = warp * 32;     // warp tile 32 x 64 (all 64 N cols)

    float acc[2][8][4];
    #pragma unroll
    for (int i = 0; i < 2; i++)
        #pragma unroll
        for (int j = 0; j < 8; j++)
            #pragma unroll
            for (int l = 0; l < 4; l++) acc[i][j][l] = 0.f;

    const int nk = K / BK;    // >= 6 everywhere

    auto loadStage = [&](int s, int buf) {
        #pragma unroll
        for (int v = 0; v < 2; v++) {
            cp16(sA + buf*A_BYTES + adst[v][0], agp[v] + s*BK);
            cp16(sA + buf*A_BYTES + adst[v][1], agp[v] + s*BK + 8);
            cp16(sB + buf*B_BYTES + bdst[v],    bgp[v] + (long)s*BK*N);
        }
        asm volatile("cp.async.commit_group;" ::: "memory");
    };

    loadStage(0, 0);
    loadStage(1, 1);

    int buf = 0;
    for (int it = 0; it < nk; ++it) {
        if (it + 1 < nk) asm volatile("cp.async.wait_group 1;" ::: "memory");
        else             asm volatile("cp.async.wait_group 0;" ::: "memory");
        __syncthreads();
        if (it + 2 < nk) {
            int nb = buf + 2; if (nb >= NSTAGE) nb -= NSTAGE;
            loadStage(it + 2, nb);
        }

        const uint32_t aB = sA + buf*A_BYTES;
        const uint32_t bB = sB + buf*B_BYTES;
        #pragma unroll
        for (int ksub = 0; ksub < 2; ksub++) {
            uint32_t afr[2][4];
            #pragma unroll
            for (int mt = 0; mt < 2; mt++) {
                int row = m_warp + mt*16 + (lane & 15);
                int ch  = ksub*2 + (lane >> 4);
                ldmx4(afr[mt], aB + row*64 + ((ch ^ ((row>>1)&3))*16));
            }
            uint32_t bfr[8][2];
            #pragma unroll
            for (int cg = 0; cg < 4; cg++) {
                int k  = ksub*16 + ((lane>>3)&1)*8 + (lane&7);
                int cn = cg*2 + (lane>>4);
                uint32_t r[4];
                ldmx4t(r, bB + k*128 + ((cn ^ (k&7))*16));
                bfr[cg*2+0][0] = r[0]; bfr[cg*2+0][1] = r[1];
                bfr[cg*2+1][0] = r[2]; bfr[cg*2+1][1] = r[3];
            }
            #pragma unroll
            for (int mt = 0; mt < 2; mt++)
                #pragma unroll
                for (int nt = 0; nt < 8; nt++)
                    mma_bf16(acc[mt][nt], afr[mt], bfr[nt]);
        }
        if (++buf == NSTAGE) buf = 0;
    }

    // ---- epilogue: warp rows m_warp..m_warp+31, all 64 cols
    const int g  = lane >> 2;
    const int tg = lane & 3;
    float* Cf = (float*)Cv;
    bf16*  Cb = (bf16*)Cv;
    #pragma unroll
    for (int mt = 0; mt < 2; mt++) {
        #pragma unroll
        for (int rh = 0; rh < 2; rh++) {
            int m = m0 + m_warp + mt*16 + rh*8 + g;
            long crow = (EPI == EPI_SCATTER_RES) ? (long)win2img(m) : (long)m;
            #pragma unroll
            for (int nt = 0; nt < 8; nt++) {
                int col = n0 + nt*8 + tg*2;
                float2 bb = *(const float2*)(bias + col);
                float v0 = acc[mt][nt][rh*2 + 0] + bb.x;
                float v1 = acc[mt][nt][rh*2 + 1] + bb.y;
                if (EPI == EPI_GELU) { v0 = gelu_f(v0); v1 = gelu_f(v1); }
                if (EPI == EPI_RES || EPI == EPI_SCATTER_RES) {
                    float2 r2 = *(const float2*)(resid + crow * N + col);
                    v0 += r2.x; v1 += r2.y;
                }
                if (OUT_BF16) {
                    bf162 o; o.x = __float2bfloat16(v0); o.y = __float2bfloat16(v1);
                    *(bf162*)(Cb + crow * N + col) = o;
                } else {
                    float2 o2 = {v0, v1};
                    *(float2*)(Cf + crow * N + col) = o2;
                }
            }
        }
    }
}

// ---------------- tensor-core windowed attention (unchanged) --------------
#define BSTR 68

__global__ void __launch_bounds__(128) attn_kernel(const bf16* __restrict__ qkv,
                                                   bf16* __restrict__ out) {
    __shared__ __align__(16) bf16 sq[64*32];
    __shared__ __align__(16) bf16 sk[64*32];
    __shared__ __align__(16) bf16 sv[64*32];
    __shared__ __align__(16) float sbias[64*BSTR];

    const int tid = threadIdx.x, lane = tid & 31, wid = tid >> 5;
    const int win = blockIdx.x, h = blockIdx.y;
    const int w = win & 63;
    const int cls = (((w >> 3) == 7) ? 2 : 0) + (((w & 7) == 7) ? 1 : 0);
    const float* gb = g_bias + ((cls*NH + h) << 12);
    const long base = (long)win * NTOK;
    const float scale = 0.17677669529663687f;

    const uint32_t sqb = (uint32_t)__cvta_generic_to_shared(sq);
    const uint32_t skb = (uint32_t)__cvta_generic_to_shared(sk);
    const uint32_t svb = (uint32_t)__cvta_generic_to_shared(sv);

    #pragma unroll
    for (int i = 0; i < 2; i++) {
        int idx = tid + i*128;
        int n = idx >> 2, ch = idx & 3;
        uint4 zq = {0,0,0,0}, zk = {0,0,0,0}, zv = {0,0,0,0};
        if (n < NTOK) {
            const bf16* p = qkv + (base + n)*(3*CC) + h*HD + ch*8;
            zq = *(const uint4*)(p);
            zk = *(const uint4*)(p + CC);
            zv = *(const uint4*)(p + 2*CC);
        }
        uint32_t off = n*64 + ((ch ^ ((n>>1)&3))*16);
        *(uint4*)((char*)sq + off) = zq;
        *(uint4*)((char*)sk + off) = zk;
        *(uint4*)((char*)sv + off) = zv;
    }
    #pragma unroll
    for (int i = 0; i < 8; i++) {
        int idx = tid + i*128;
        int row = idx >> 4, c4 = idx & 15;
        *(float4*)&sbias[row*BSTR + c4*4] = *(const float4*)(gb + row*64 + c4*4);
    }
    __syncthreads();

    float s[8][4];
    #pragma unroll
    for (int i = 0; i < 8; i++)
        #pragma unroll
        for (int j = 0; j < 4; j++) s[i][j] = 0.f;

    #pragma unroll
    for (int ksub = 0; ksub < 2; ksub++) {
        uint32_t a[4];
        {
            int row = wid*16 + (lane & 15);
            int ch  = ksub*2 + (lane >> 4);
            ldmx4(a, sqb + row*64 + ((ch ^ ((row>>1)&3))*16));
        }
        #pragma unroll
        for (int bt = 0; bt < 4; bt++) {
            int n  = bt*16 + ((lane>>4)&1)*8 + (lane & 7);
            int ch = ksub*2 + ((lane>>3)&1);
            uint32_t r[4];
            ldmx4(r, skb + n*64 + ((ch ^ ((n>>1)&3))*16));
            uint32_t b0[2] = {r[0], r[1]}, b1[2] = {r[2], r[3]};
            mma_bf16(s[bt*2+0], a, b0);
            mma_bf16(s[bt*2+1], a, b1);
        }
    }

    const int g  = lane >> 2, tg = lane & 3;
    const int r0 = wid*16 + g, r1 = r0 + 8;
    float mx0 = -1e30f, mx1 = -1e30f;
    #pragma unroll
    for (int nt = 0; nt < 8; nt++) {
        float2 b0 = *(const float2*)&sbias[r0*BSTR + nt*8 + tg*2];
        float2 b1 = *(const float2*)&sbias[r1*BSTR + nt*8 + tg*2];
        s[nt][0] = fmaf(s[nt][0], scale, b0.x);
        s[nt][1] = fmaf(s[nt][1], scale, b0.y);
        s[nt][2] = fmaf(s[nt][2], scale, b1.x);
        s[nt][3] = fmaf(s[nt][3], scale, b1.y);
        mx0 = fmaxf(mx0, fmaxf(s[nt][0], s[nt][1]));
        mx1 = fmaxf(mx1, fmaxf(s[nt][2], s[nt][3]));
    }
    mx0 = fmaxf(mx0, __shfl_xor_sync(~0u, mx0, 1));
    mx0 = fmaxf(mx0, __shfl_xor_sync(~0u, mx0, 2));
    mx1 = fmaxf(mx1, __shfl_xor_sync(~0u, mx1, 1));
    mx1 = fmaxf(mx1, __shfl_xor_sync(~0u, mx1, 2));
    float sum0 = 0.f, sum1 = 0.f;
    #pragma unroll
    for (int nt = 0; nt < 8; nt++) {
        s[nt][0] = __expf(s[nt][0] - mx0);
        s[nt][1] = __expf(s[nt][1] - mx0);
        s[nt][2] = __expf(s[nt][2] - mx1);
        s[nt][3] = __expf(s[nt][3] - mx1);
        sum0 += s[nt][0] + s[nt][1];
        sum1 += s[nt][2] + s[nt][3];
    }
    sum0 += __shfl_xor_sync(~0u, sum0, 1);
    sum0 += __shfl_xor_sync(~0u, sum0, 2);
    sum1 += __shfl_xor_sync(~0u, sum1, 1);
    sum1 += __shfl_xor_sync(~0u, sum1, 2);
    const float inv0 = 1.f / sum0, inv1 = 1.f / sum1;

    uint32_t pk[4][4];
    #pragma unroll
    for (int kt = 0; kt < 4; kt++) {
        pk[kt][0] = packbf(s[2*kt  ][0], s[2*kt  ][1]);
        pk[kt][1] = packbf(s[2*kt  ][2], s[2*kt  ][3]);
        pk[kt][2] = packbf(s[2*kt+1][0], s[2*kt+1][1]);
        pk[kt][3] = packbf(s[2*kt+1][2], s[2*kt+1][3]);
    }

    float o[4][4];
    #pragma unroll
    for (int i = 0; i < 4; i++)
        #pragma unroll
        for (int j = 0; j < 4; j++) o[i][j] = 0.f;

    #pragma unroll
    for (int kt = 0; kt < 4; kt++) {
        #pragma unroll
        for (int pr = 0; pr < 2; pr++) {
            int k  = kt*16 + ((lane>>3)&1)*8 + (lane & 7);
            int cn = pr*2 + ((lane>>4)&1);
            uint32_t r[4];
            ldmx4t(r, svb + k*64 + ((cn ^ ((k>>1)&3))*16));
            uint32_t b0[2] = {r[0], r[1]}, b1[2] = {r[2], r[3]};
            mma_bf16(o[pr*2+0], pk[kt], b0);
            mma_bf16(o[pr*2+1], pk[kt], b1);
        }
    }

    #pragma unroll
    for (int nt = 0; nt < 4; nt++) {
        int col = h*HD + nt*8 + tg*2;
        if (r0 < NTOK) {
            bf162 t; t.x = __float2bfloat16(o[nt][0]*inv0); t.y = __float2bfloat16(o[nt][1]*inv0);
            *(bf162*)(out + (base + r0)*CC + col) = t;
        }
        if (r1 < NTOK) {
            bf162 t; t.x = __float2bfloat16(o[nt][2]*inv1); t.y = __float2bfloat16(o[nt][3]*inv1);
            *(bf162*)(out + (base + r1)*CC + col) = t;
        }
    }
}

// ---------------- launch ----------------
extern "C" void kernel_launch(void* const* d_in, const int* in_sizes, int n_in,
                              void* d_out, int out_size) {
    const float* x       = (const float*)d_in[0];
    const float* n1g     = (const float*)d_in[1];
    const float* n1b     = (const float*)d_in[2];
    const float* qkv_w   = (const float*)d_in[3];
    const float* qkv_b   = (const float*)d_in[4];
    const float* rpb     = (const float*)d_in[5];
    const float* proj_w  = (const float*)d_in[6];
    const float* proj_b  = (const float*)d_in[7];
    const float* n2g     = (const float*)d_in[8];
    const float* n2b     = (const float*)d_in[9];
    const float* fc1_w   = (const float*)d_in[10];
    const float* fc1_b   = (const float*)d_in[11];
    const float* fc2_w   = (const float*)d_in[12];
    const float* fc2_b   = (const float*)d_in[13];
    float* out = (float*)d_out;

    bf16 *xn, *qkv, *attn, *xn2, *hbuf, *wq, *wp, *w1, *w2;
    float *y;
    cudaGetSymbolAddress((void**)&xn,   g_xn_h);
    cudaGetSymbolAddress((void**)&qkv,  g_qkv_h);
    cudaGetSymbolAddress((void**)&attn, g_attn_h);
    cudaGetSymbolAddress((void**)&y,    g_y);
    cudaGetSymbolAddress((void**)&xn2,  g_xn2_h);
    cudaGetSymbolAddress((void**)&hbuf, g_h_h);
    cudaGetSymbolAddress((void**)&wq,   g_wq);
    cudaGetSymbolAddress((void**)&wp,   g_wp);
    cudaGetSymbolAddress((void**)&w1,   g_w1);
    cudaGetSymbolAddress((void**)&w2,   g_w2);

    f2bf_all<<<(WTOT+255)/256, 256>>>(qkv_w, proj_w, fc1_w, fc2_w, wq, wp, w1, w2);
    bias_precompute<<<(4*NH*4096)/256, 256>>>(rpb);

    const int mblk = MROWS / BM;   // 784

    ln_kernel<<<MROWS/8, 256>>>(x, n1g, n1b, xn);
    tgemm<EPI_NONE, true, true><<<dim3(3*CC/BN, mblk), 128>>>(xn, wq, qkv_b, qkv, nullptr, 3*CC, CC);
    attn_kernel<<<dim3(BATCH*NWIN, NH), 128>>>(qkv, attn);
    tgemm<EPI_SCATTER_RES, false, false><<<dim3(CC/BN, mblk), 128>>>(attn, wp, proj_b, y, x, CC, CC);
    ln_kernel<<<MROWS/8, 256>>>(y, n2g, n2b, xn2);
    tgemm<EPI_GELU, false, true><<<dim3(HID/BN, mblk), 128>>>(xn2, w1, fc1_b, hbuf, nullptr, HID, CC);
    tgemm<EPI_RES, false, false><<<dim3(CC/BN, mblk), 128>>>(hbuf, w2, fc2_b, out, y, CC, HID);
}

// round 12
// speedup vs baseline: 6.5755x; 1.0652x over previous
// R12: CUTLASS-style 64x64 warp tiles (2 warps / 64 threads per CTA) —
// 4:1 mma:ldmatrix, ILP over occupancy. Loads/swizzles/ring from R11 (verified).
#include <cuda_runtime.h>
#include <cuda_bf16.h>
#include <math.h>
#include <stdint.h>

#define BATCH 32
#define HH 56
#define WW2 56
#define CC 192
#define HID 768
#define WS 7
#define SS 3
#define NH 6
#define HD 32
#define NTOK 49
#define NWIN 64
#define MROWS (BATCH*HH*WW2)
#define ROWS_PER_BATCH (NWIN*NTOK)

typedef __nv_bfloat16 bf16;
typedef __nv_bfloat162 bf162;

// ---------------- scratch ----------------
__device__ bf16  g_xn_h [MROWS*CC];
__device__ bf16  g_qkv_h[(long)MROWS*3*CC];
__device__ bf16  g_attn_h[MROWS*CC];
__device__ float g_y    [MROWS*CC];
__device__ bf16  g_xn2_h[MROWS*CC];
__device__ bf16  g_h_h  [(long)MROWS*HID];
__device__ bf16  g_wq[CC*3*CC];
__device__ bf16  g_wp[CC*CC];
__device__ bf16  g_w1[CC*HID];
__device__ bf16  g_w2[HID*CC];
__device__ float g_bias[4*NH*64*64];

__device__ __forceinline__ int win2img(int r) {
    int b   = r / ROWS_PER_BATCH;
    int rem = r - b * ROWS_PER_BATCH;
    int w   = rem / NTOK;
    int n   = rem - w * NTOK;
    int i = n / WS, j = n - WS * (n / WS);
    int hs = (w >> 3) * WS + i;
    int ws = (w & 7) * WS + j;
    int h  = hs + SS; if (h  >= HH)  h  -= HH;
    int wc = ws + SS; if (wc >= WW2) wc -= WW2;
    return (b * HH + h) * WW2 + wc;
}

// ---------------- fp32 -> bf16 conversion for all four weights ------------
#define WQ_N (CC*3*CC)
#define WP_N (CC*CC)
#define W1_N (CC*HID)
#define W2_N (HID*CC)
#define WTOT (WQ_N+WP_N+W1_N+W2_N)
__global__ void f2bf_all(const float* __restrict__ s0, const float* __restrict__ s1,
                         const float* __restrict__ s2, const float* __restrict__ s3,
                         bf16* d0, bf16* d1, bf16* d2, bf16* d3) {
    int i = blockIdx.x * 256 + threadIdx.x;
    if (i < WQ_N) { d0[i] = __float2bfloat16(s0[i]); return; }
    i -= WQ_N;
    if (i < WP_N) { d1[i] = __float2bfloat16(s1[i]); return; }
    i -= WP_N;
    if (i < W1_N) { d2[i] = __float2bfloat16(s2[i]); return; }
    i -= W1_N;
    if (i < W2_N) { d3[i] = __float2bfloat16(s3[i]); }
}

// ---------------- attention bias table ----------------
__global__ void bias_precompute(const float* __restrict__ rpb) {
    int idx = blockIdx.x * 256 + threadIdx.x;
    int cls = idx / (NH*4096);
    int rem = idx - cls*NH*4096;
    int h   = rem >> 12;
    int p   = rem & 4095;
    int n = p >> 6, m = p & 63;
    float v;
    if (m >= NTOK) v = -1e9f;
    else if (n >= NTOK) v = 0.f;
    else {
        int in_ = n / WS, jn = n % WS, im = m / WS, jm = m % WS;
        v = rpb[((in_-im+6)*13 + (jn-jm+6))*NH + h];
        int rE = cls >> 1, cE = cls & 1;
        int rn = rE ? (in_ < 4 ? 1 : 2) : 0;
        int cn = cE ? (jn  < 4 ? 1 : 2) : 0;
        int rm = rE ? (im  < 4 ? 1 : 2) : 0;
        int cm = cE ? (jm  < 4 ? 1 : 2) : 0;
        if (rn*3+cn != rm*3+cm) v -= 100.f;
    }
    g_bias[idx] = v;
}

// ---------------- LayerNorm ----------------
__global__ void ln_kernel(const float* __restrict__ x, const float* __restrict__ g,
                          const float* __restrict__ b, bf16* __restrict__ o) {
    int row  = blockIdx.x * 8 + (threadIdx.x >> 5);
    int lane = threadIdx.x & 31;
    const float* p = x + (long)row * CC;
    float v[6];
    float s = 0.f;
    #pragma unroll
    for (int i = 0; i < 6; i++) { v[i] = p[lane + 32*i]; s += v[i]; }
    #pragma unroll
    for (int off = 16; off; off >>= 1) s += __shfl_xor_sync(~0u, s, off);
    float mu = s * (1.f/192.f);
    float vs = 0.f;
    #pragma unroll
    for (int i = 0; i < 6; i++) { float d = v[i]-mu; vs += d*d; }
    #pragma unroll
    for (int off = 16; off; off >>= 1) vs += __shfl_xor_sync(~0u, vs, off);
    float r = rsqrtf(vs * (1.f/192.f) + 1e-5f);
    bf16* op = o + (long)row * CC;
    #pragma unroll
    for (int i = 0; i < 6; i++) {
        int c = lane + 32*i;
        op[c] = __float2bfloat16((v[i]-mu) * r * g[c] + b[c]);
    }
}

// ---------------- helpers ----------------
__device__ __forceinline__ void mma_bf16(float* c, const uint32_t* a, const uint32_t* b) {
    asm volatile("mma.sync.aligned.m16n8k16.row.col.f32.bf16.bf16.f32 "
        "{%0,%1,%2,%3},{%4,%5,%6,%7},{%8,%9},{%0,%1,%2,%3};"
        : "+f"(c[0]), "+f"(c[1]), "+f"(c[2]), "+f"(c[3])
        : "r"(a[0]), "r"(a[1]), "r"(a[2]), "r"(a[3]), "r"(b[0]), "r"(b[1]));
}
__device__ __forceinline__ void ldmx4(uint32_t* r, uint32_t addr) {
    asm volatile("ldmatrix.sync.aligned.m8n8.x4.shared.b16 {%0,%1,%2,%3}, [%4];"
        : "=r"(r[0]), "=r"(r[1]), "=r"(r[2]), "=r"(r[3]) : "r"(addr));
}
__device__ __forceinline__ void ldmx4t(uint32_t* r, uint32_t addr) {
    asm volatile("ldmatrix.sync.aligned.m8n8.x4.trans.shared.b16 {%0,%1,%2,%3}, [%4];"
        : "=r"(r[0]), "=r"(r[1]), "=r"(r[2]), "=r"(r[3]) : "r"(addr));
}
__device__ __forceinline__ void cp16(uint32_t smem, const void* g) {
    asm volatile("cp.async.cg.shared.global [%0], [%1], 16;" :: "r"(smem), "l"(g));
}
__device__ __forceinline__ uint32_t packbf(float lo, float hi) {
    bf162 t; t.x = __float2bfloat16(lo); t.y = __float2bfloat16(hi);
    return *(uint32_t*)&t;
}

// ---------------- bf16 mma GEMM: 128x64 block, 2 warps x (64x64) ----------
#define BM 128
#define BN 64
#define BK 32
#define A_BYTES (BM*64)      // 8192 per stage
#define B_BYTES (BK*128)     // 4096 per stage
#define NSTAGE 3

enum { EPI_NONE = 0, EPI_GELU = 1, EPI_RES = 2, EPI_SCATTER_RES = 3 };

__device__ __forceinline__ float gelu_f(float x) {
    return 0.5f * x * (1.0f + erff(x * 0.70710678118654752f));
}

template<int EPI, bool GATHER_A, bool OUT_BF16>
__global__ void __launch_bounds__(64) tgemm(const bf16* __restrict__ A,
                                            const bf16* __restrict__ Bm,
                                            const float* __restrict__ bias,
                                            void* __restrict__ Cv,
                                            const float* __restrict__ resid,
                                            int N, int K) {
    __shared__ char smemA[NSTAGE*A_BYTES];
    __shared__ char smemB[NSTAGE*B_BYTES];
    const uint32_t sA = (uint32_t)__cvta_generic_to_shared(smemA);
    const uint32_t sB = (uint32_t)__cvta_generic_to_shared(smemB);
    const int tid = threadIdx.x, lane = tid & 31, warp = tid >> 5;
    const int m0 = blockIdx.y * BM;
    const int n0 = blockIdx.x * BN;

    // ---- A tile load map: 512 16B chunks; thread -> rows tid>>2 + 16v, chunk tid&3
    const int ar0 = tid >> 2;
    const int ach = tid & 3;
    const bf16* agp[8];
    uint32_t adst[8];
    #pragma unroll
    for (int v = 0; v < 8; v++) {
        int row = ar0 + 16*v;
        agp[v] = A + (long)(GATHER_A ? win2img(m0 + row) : (m0 + row)) * K + ach*8;
        adst[v] = row*64 + (uint32_t)(((ach ^ ((row>>1)&3)))*16);
    }
    // ---- B tile load map: 256 chunks; thread -> k rows tid>>3 + 8v, chunk tid&7
    const int bk0 = tid >> 3;
    const int bch = tid & 7;
    const bf16* bgp[4];
    uint32_t bdst[4];
    #pragma unroll
    for (int v = 0; v < 4; v++) {
        int bk = bk0 + 8*v;
        bgp[v] = Bm + (long)bk * N + n0 + bch*8;
        bdst[v] = bk*128 + (uint32_t)((bch ^ (bk & 7))*16);
    }

    const int m_warp = warp * 64;     // warp tile 64 x 64

    float acc[4][8][4];
    #pragma unroll
    for (int i = 0; i < 4; i++)
        #pragma unroll
        for (int j = 0; j < 8; j++)
            #pragma unroll
            for (int l = 0; l < 4; l++) acc[i][j][l] = 0.f;

    const int nk = K / BK;    // >= 6

    auto loadStage = [&](int s, int buf) {
        #pragma unroll
        for (int v = 0; v < 8; v++)
            cp16(sA + buf*A_BYTES + adst[v], agp[v] + s*BK);
        #pragma unroll
        for (int v = 0; v < 4; v++)
            cp16(sB + buf*B_BYTES + bdst[v], bgp[v] + (long)s*BK*N);
        asm volatile("cp.async.commit_group;" ::: "memory");
    };

    loadStage(0, 0);
    loadStage(1, 1);

    int buf = 0;
    for (int it = 0; it < nk; ++it) {
        if (it + 1 < nk) asm volatile("cp.async.wait_group 1;" ::: "memory");
        else             asm volatile("cp.async.wait_group 0;" ::: "memory");
        __syncthreads();
        if (it + 2 < nk) {
            int nb = buf + 2; if (nb >= NSTAGE) nb -= NSTAGE;
            loadStage(it + 2, nb);
        }

        const uint32_t aB = sA + buf*A_BYTES;
        const uint32_t bB = sB + buf*B_BYTES;
        #pragma unroll
        for (int ksub = 0; ksub < 2; ksub++) {
            uint32_t afr[4][4];
            #pragma unroll
            for (int mt = 0; mt < 4; mt++) {
                int row = m_warp + mt*16 + (lane & 15);
                int ch  = ksub*2 + (lane >> 4);
                ldmx4(afr[mt], aB + row*64 + ((ch ^ ((row>>1)&3))*16));
            }
            uint32_t bfr[8][2];
            #pragma unroll
            for (int cg = 0; cg < 4; cg++) {
                int k  = ksub*16 + ((lane>>3)&1)*8 + (lane&7);
                int cn = cg*2 + (lane>>4);
                uint32_t r[4];
                ldmx4t(r, bB + k*128 + ((cn ^ (k&7))*16));
                bfr[cg*2+0][0] = r[0]; bfr[cg*2+0][1] = r[1];
                bfr[cg*2+1][0] = r[2]; bfr[cg*2+1][1] = r[3];
            }
            #pragma unroll
            for (int mt = 0; mt < 4; mt++)
                #pragma unroll
                for (int nt = 0; nt < 8; nt++)
                    mma_bf16(acc[mt][nt], afr[mt], bfr[nt]);
        }
        if (++buf == NSTAGE) buf = 0;
    }

    // ---- epilogue: warp rows m_warp..m_warp+63, all 64 cols
    const int g  = lane >> 2;
    const int tg = lane & 3;
    float* Cf = (float*)Cv;
    bf16*  Cb = (bf16*)Cv;
    #pragma unroll
    for (int mt = 0; mt < 4; mt++) {
        #pragma unroll
        for (int rh = 0; rh < 2; rh++) {
            int m = m0 + m_warp + mt*16 + rh*8 + g;
            long crow = (EPI == EPI_SCATTER_RES) ? (long)win2img(m) : (long)m;
            #pragma unroll
            for (int nt = 0; nt < 8; nt++) {
                int col = n0 + nt*8 + tg*2;
                float2 bb = *(const float2*)(bias + col);
                float v0 = acc[mt][nt][rh*2 + 0] + bb.x;
                float v1 = acc[mt][nt][rh*2 + 1] + bb.y;
                if (EPI == EPI_GELU) { v0 = gelu_f(v0); v1 = gelu_f(v1); }
                if (EPI == EPI_RES || EPI == EPI_SCATTER_RES) {
                    float2 r2 = *(const float2*)(resid + crow * N + col);
                    v0 += r2.x; v1 += r2.y;
                }
                if (OUT_BF16) {
                    bf162 o; o.x = __float2bfloat16(v0); o.y = __float2bfloat16(v1);
                    *(bf162*)(Cb + crow * N + col) = o;
                } else {
                    float2 o2 = {v0, v1};
                    *(float2*)(Cf + crow * N + col) = o2;
                }
            }
        }
    }
}

// ---------------- tensor-core windowed attention (unchanged) --------------
#define BSTR 68

__global__ void __launch_bounds__(128) attn_kernel(const bf16* __restrict__ qkv,
                                                   bf16* __restrict__ out) {
    __shared__ __align__(16) bf16 sq[64*32];
    __shared__ __align__(16) bf16 sk[64*32];
    __shared__ __align__(16) bf16 sv[64*32];
    __shared__ __align__(16) float sbias[64*BSTR];

    const int tid = threadIdx.x, lane = tid & 31, wid = tid >> 5;
    const int win = blockIdx.x, h = blockIdx.y;
    const int w = win & 63;
    const int cls = (((w >> 3) == 7) ? 2 : 0) + (((w & 7) == 7) ? 1 : 0);
    const float* gb = g_bias + ((cls*NH + h) << 12);
    const long base = (long)win * NTOK;
    const float scale = 0.17677669529663687f;

    const uint32_t sqb = (uint32_t)__cvta_generic_to_shared(sq);
    const uint32_t skb = (uint32_t)__cvta_generic_to_shared(sk);
    const uint32_t svb = (uint32_t)__cvta_generic_to_shared(sv);

    #pragma unroll
    for (int i = 0; i < 2; i++) {
        int idx = tid + i*128;
        int n = idx >> 2, ch = idx & 3;
        uint4 zq = {0,0,0,0}, zk = {0,0,0,0}, zv = {0,0,0,0};
        if (n < NTOK) {
            const bf16* p = qkv + (base + n)*(3*CC) + h*HD + ch*8;
            zq = *(const uint4*)(p);
            zk = *(const uint4*)(p + CC);
            zv = *(const uint4*)(p + 2*CC);
        }
        uint32_t off = n*64 + ((ch ^ ((n>>1)&3))*16);
        *(uint4*)((char*)sq + off) = zq;
        *(uint4*)((char*)sk + off) = zk;
        *(uint4*)((char*)sv + off) = zv;
    }
    #pragma unroll
    for (int i = 0; i < 8; i++) {
        int idx = tid + i*128;
        int row = idx >> 4, c4 = idx & 15;
        *(float4*)&sbias[row*BSTR + c4*4] = *(const float4*)(gb + row*64 + c4*4);
    }
    __syncthreads();

    float s[8][4];
    #pragma unroll
    for (int i = 0; i < 8; i++)
        #pragma unroll
        for (int j = 0; j < 4; j++) s[i][j] = 0.f;

    #pragma unroll
    for (int ksub = 0; ksub < 2; ksub++) {
        uint32_t a[4];
        {
            int row = wid*16 + (lane & 15);
            int ch  = ksub*2 + (lane >> 4);
            ldmx4(a, sqb + row*64 + ((ch ^ ((row>>1)&3))*16));
        }
        #pragma unroll
        for (int bt = 0; bt < 4; bt++) {
            int n  = bt*16 + ((lane>>4)&1)*8 + (lane & 7);
            int ch = ksub*2 + ((lane>>3)&1);
            uint32_t r[4];
            ldmx4(r, skb + n*64 + ((ch ^ ((n>>1)&3))*16));
            uint32_t b0[2] = {r[0], r[1]}, b1[2] = {r[2], r[3]};
            mma_bf16(s[bt*2+0], a, b0);
            mma_bf16(s[bt*2+1], a, b1);
        }
    }

    const int g  = lane >> 2, tg = lane & 3;
    const int r0 = wid*16 + g, r1 = r0 + 8;
    float mx0 = -1e30f, mx1 = -1e30f;
    #pragma unroll
    for (int nt = 0; nt < 8; nt++) {
        float2 b0 = *(const float2*)&sbias[r0*BSTR + nt*8 + tg*2];
        float2 b1 = *(const float2*)&sbias[r1*BSTR + nt*8 + tg*2];
        s[nt][0] = fmaf(s[nt][0], scale, b0.x);
        s[nt][1] = fmaf(s[nt][1], scale, b0.y);
        s[nt][2] = fmaf(s[nt][2], scale, b1.x);
        s[nt][3] = fmaf(s[nt][3], scale, b1.y);
        mx0 = fmaxf(mx0, fmaxf(s[nt][0], s[nt][1]));
        mx1 = fmaxf(mx1, fmaxf(s[nt][2], s[nt][3]));
    }
    mx0 = fmaxf(mx0, __shfl_xor_sync(~0u, mx0, 1));
    mx0 = fmaxf(mx0, __shfl_xor_sync(~0u, mx0, 2));
    mx1 = fmaxf(mx1, __shfl_xor_sync(~0u, mx1, 1));
    mx1 = fmaxf(mx1, __shfl_xor_sync(~0u, mx1, 2));
    float sum0 = 0.f, sum1 = 0.f;
    #pragma unroll
    for (int nt = 0; nt < 8; nt++) {
        s[nt][0] = __expf(s[nt][0] - mx0);
        s[nt][1] = __expf(s[nt][1] - mx0);
        s[nt][2] = __expf(s[nt][2] - mx1);
        s[nt][3] = __expf(s[nt][3] - mx1);
        sum0 += s[nt][0] + s[nt][1];
        sum1 += s[nt][2] + s[nt][3];
    }
    sum0 += __shfl_xor_sync(~0u, sum0, 1);
    sum0 += __shfl_xor_sync(~0u, sum0, 2);
    sum1 += __shfl_xor_sync(~0u, sum1, 1);
    sum1 += __shfl_xor_sync(~0u, sum1, 2);
    const float inv0 = 1.f / sum0, inv1 = 1.f / sum1;

    uint32_t pk[4][4];
    #pragma unroll
    for (int kt = 0; kt < 4; kt++) {
        pk[kt][0] = packbf(s[2*kt  ][0], s[2*kt  ][1]);
        pk[kt][1] = packbf(s[2*kt  ][2], s[2*kt  ][3]);
        pk[kt][2] = packbf(s[2*kt+1][0], s[2*kt+1][1]);
        pk[kt][3] = packbf(s[2*kt+1][2], s[2*kt+1][3]);
    }

    float o[4][4];
    #pragma unroll
    for (int i = 0; i < 4; i++)
        #pragma unroll
        for (int j = 0; j < 4; j++) o[i][j] = 0.f;

    #pragma unroll
    for (int kt = 0; kt < 4; kt++) {
        #pragma unroll
        for (int pr = 0; pr < 2; pr++) {
            int k  = kt*16 + ((lane>>3)&1)*8 + (lane & 7);
            int cn = pr*2 + ((lane>>4)&1);
            uint32_t r[4];
            ldmx4t(r, svb + k*64 + ((cn ^ ((k>>1)&3))*16));
            uint32_t b0[2] = {r[0], r[1]}, b1[2] = {r[2], r[3]};
            mma_bf16(o[pr*2+0], pk[kt], b0);
            mma_bf16(o[pr*2+1], pk[kt], b1);
        }
    }

    #pragma unroll
    for (int nt = 0; nt < 4; nt++) {
        int col = h*HD + nt*8 + tg*2;
        if (r0 < NTOK) {
            bf162 t; t.x = __float2bfloat16(o[nt][0]*inv0); t.y = __float2bfloat16(o[nt][1]*inv0);
            *(bf162*)(out + (base + r0)*CC + col) = t;
        }
        if (r1 < NTOK) {
            bf162 t; t.x = __float2bfloat16(o[nt][2]*inv1); t.y = __float2bfloat16(o[nt][3]*inv1);
            *(bf162*)(out + (base + r1)*CC + col) = t;
        }
    }
}

// ---------------- launch ----------------
extern "C" void kernel_launch(void* const* d_in, const int* in_sizes, int n_in,
                              void* d_out, int out_size) {
    const float* x       = (const float*)d_in[0];
    const float* n1g     = (const float*)d_in[1];
    const float* n1b     = (const float*)d_in[2];
    const float* qkv_w   = (const float*)d_in[3];
    const float* qkv_b   = (const float*)d_in[4];
    const float* rpb     = (const float*)d_in[5];
    const float* proj_w  = (const float*)d_in[6];
    const float* proj_b  = (const float*)d_in[7];
    const float* n2g     = (const float*)d_in[8];
    const float* n2b     = (const float*)d_in[9];
    const float* fc1_w   = (const float*)d_in[10];
    const float* fc1_b   = (const float*)d_in[11];
    const float* fc2_w   = (const float*)d_in[12];
    const float* fc2_b   = (const float*)d_in[13];
    float* out = (float*)d_out;

    bf16 *xn, *qkv, *attn, *xn2, *hbuf, *wq, *wp, *w1, *w2;
    float *y;
    cudaGetSymbolAddress((void**)&xn,   g_xn_h);
    cudaGetSymbolAddress((void**)&qkv,  g_qkv_h);
    cudaGetSymbolAddress((void**)&attn, g_attn_h);
    cudaGetSymbolAddress((void**)&y,    g_y);
    cudaGetSymbolAddress((void**)&xn2,  g_xn2_h);
    cudaGetSymbolAddress((void**)&hbuf, g_h_h);
    cudaGetSymbolAddress((void**)&wq,   g_wq);
    cudaGetSymbolAddress((void**)&wp,   g_wp);
    cudaGetSymbolAddress((void**)&w1,   g_w1);
    cudaGetSymbolAddress((void**)&w2,   g_w2);

    f2bf_all<<<(WTOT+255)/256, 256>>>(qkv_w, proj_w, fc1_w, fc2_w, wq, wp, w1, w2);
    bias_precompute<<<(4*NH*4096)/256, 256>>>(rpb);

    const int mblk = MROWS / BM;   // 784

    ln_kernel<<<MROWS/8, 256>>>(x, n1g, n1b, xn);
    tgemm<EPI_NONE, true, true><<<dim3(3*CC/BN, mblk), 64>>>(xn, wq, qkv_b, qkv, nullptr, 3*CC, CC);
    attn_kernel<<<dim3(BATCH*NWIN, NH), 128>>>(qkv, attn);
    tgemm<EPI_SCATTER_RES, false, false><<<dim3(CC/BN, mblk), 64>>>(attn, wp, proj_b, y, x, CC, CC);
    ln_kernel<<<MROWS/8, 256>>>(y, n2g, n2b, xn2);
    tgemm<EPI_GELU, false, true><<<dim3(HID/BN, mblk), 64>>>(xn2, w1, fc1_b, hbuf, nullptr, HID, CC);
    tgemm<EPI_RES, false, false><<<dim3(CC/BN, mblk), 64>>>(hbuf, w2, fc2_b, out, y, CC, HID);
}